// round 12
// baseline (speedup 1.0000x reference)
#include <cuda_runtime.h>
#include <cuda_bf16.h>
#include <math.h>
#include <stdint.h>

#define Bsz 4
#define Sq  1024
#define Fd  1024
#define Hh  16
#define Dd  64

// ---------------------------------------------------------------------------
// Scratch (device globals)
// ---------------------------------------------------------------------------
__device__ __nv_bfloat16 g_xhi[Bsz*Sq*Fd];
__device__ __nv_bfloat16 g_xlo[Bsz*Sq*Fd];
__device__ __nv_bfloat16 g_wthi[4*Fd*Fd];   // [N][K] x4 (Wq,Wk,Wv,Wo)
__device__ __nv_bfloat16 g_wtlo[4*Fd*Fd];
__device__ __nv_bfloat16 g_qh[Bsz*Hh*Sq*Dd];
__device__ __nv_bfloat16 g_ql[Bsz*Hh*Sq*Dd];
__device__ __nv_bfloat16 g_kh[Bsz*Hh*Sq*Dd];
__device__ __nv_bfloat16 g_kl[Bsz*Hh*Sq*Dd];
__device__ __nv_bfloat16 g_vh[Bsz*Hh*Sq*Dd];
__device__ __nv_bfloat16 g_vl[Bsz*Hh*Sq*Dd];
__device__ __nv_bfloat16 g_yhi[Bsz*Sq*Fd];
__device__ __nv_bfloat16 g_ylo[Bsz*Sq*Fd];

// ---------------------------------------------------------------------------
// PTX helpers (baseline PTX only)
// ---------------------------------------------------------------------------
__device__ __forceinline__ uint32_t smem_u32(const void* p) {
    uint32_t a;
    asm("{ .reg .u64 t; cvta.to.shared.u64 t, %1; cvt.u32.u64 %0, t; }"
        : "=r"(a) : "l"(p));
    return a;
}

#define CPA(dst, src) do {                                                   \
    uint64_t _g = __cvta_generic_to_global((const void*)(src));              \
    asm volatile("cp.async.ca.shared.global [%0], [%1], 16;"                 \
                 :: "r"(dst), "l"(_g) : "memory");                           \
} while (0)
#define CPC() asm volatile("cp.async.commit_group;" ::: "memory")
#define CPW0() asm volatile("cp.async.wait_group 0;" ::: "memory")
#define CPW1() asm volatile("cp.async.wait_group 1;" ::: "memory")

__device__ __forceinline__ void ldsm4(uint32_t r[4], uint32_t addr) {
    asm volatile("ldmatrix.sync.aligned.m8n8.x4.shared.b16 {%0,%1,%2,%3}, [%4];"
        : "=r"(r[0]), "=r"(r[1]), "=r"(r[2]), "=r"(r[3]) : "r"(addr));
}
__device__ __forceinline__ void ldsm4t(uint32_t r[4], uint32_t addr) {
    asm volatile("ldmatrix.sync.aligned.m8n8.x4.trans.shared.b16 {%0,%1,%2,%3}, [%4];"
        : "=r"(r[0]), "=r"(r[1]), "=r"(r[2]), "=r"(r[3]) : "r"(addr));
}

__device__ __forceinline__ void mma16816(float* c, const uint32_t* a,
                                         uint32_t b0, uint32_t b1) {
    asm volatile("mma.sync.aligned.m16n8k16.row.col.f32.bf16.bf16.f32 "
        "{%0,%1,%2,%3}, {%4,%5,%6,%7}, {%8,%9}, {%0,%1,%2,%3};"
        : "+f"(c[0]), "+f"(c[1]), "+f"(c[2]), "+f"(c[3])
        : "r"(a[0]), "r"(a[1]), "r"(a[2]), "r"(a[3]), "r"(b0), "r"(b1));
}

// ---------------------------------------------------------------------------
// Conversions
// ---------------------------------------------------------------------------
__global__ void split_x(const float* __restrict__ X) {
    int i = (blockIdx.x * blockDim.x + threadIdx.x) * 4;
    float4 v = *reinterpret_cast<const float4*>(&X[i]);
    float vv[4] = {v.x, v.y, v.z, v.w};
#pragma unroll
    for (int j = 0; j < 4; j++) {
        __nv_bfloat16 h = __float2bfloat16(vv[j]);
        g_xhi[i + j] = h;
        g_xlo[i + j] = __float2bfloat16(vv[j] - __bfloat162float(h));
    }
}

__global__ void split_wt(const float* __restrict__ Wq, const float* __restrict__ Wk,
                         const float* __restrict__ Wv, const float* __restrict__ Wo) {
    __shared__ float t[32][33];
    const int z = blockIdx.z;
    const float* __restrict__ W = (z == 0) ? Wq : (z == 1) ? Wk : (z == 2) ? Wv : Wo;
    __nv_bfloat16* hi = g_wthi + (size_t)z * Fd * Fd;
    __nv_bfloat16* lo = g_wtlo + (size_t)z * Fd * Fd;

    const int tx = threadIdx.x, ty = threadIdx.y;
    const int kbase = blockIdx.y * 32, nbase = blockIdx.x * 32;
#pragma unroll
    for (int i = 0; i < 4; i++) {
        int kr = ty * 4 + i;
        t[kr][tx] = W[(size_t)(kbase + kr) * Fd + nbase + tx];
    }
    __syncthreads();
#pragma unroll
    for (int i = 0; i < 4; i++) {
        int nr = ty * 4 + i;
        float v = t[tx][nr];
        __nv_bfloat16 h = __float2bfloat16(v);
        size_t o = (size_t)(nbase + nr) * Fd + kbase + tx;
        hi[o] = h;
        lo[o] = __float2bfloat16(v - __bfloat162float(h));
    }
}

// ---------------------------------------------------------------------------
// mma.sync GEMM: bf16 3-term hi/lo, 3-stage cp.async ring, XOR-swizzled smem.
// BM=128, BN=256, BK=32, 8 warps (2m x 4n), warp tile 64x64.
// Stage (49152 B): Ah[0,8K) Al[8K,16K) Bh[16K,32K) Bl[32K,48K).
// ---------------------------------------------------------------------------
#define GSTG  49152
#define GSMEM (3*GSTG)

template<int MODE>
__device__ __forceinline__ void gemm_mma(
    const __nv_bfloat16* __restrict__ Ahi, const __nv_bfloat16* __restrict__ Alo,
    const __nv_bfloat16* __restrict__ Bhi, const __nv_bfloat16* __restrict__ Blo,
    const float* __restrict__ bias, float scale,
    float* __restrict__ C, __nv_bfloat16* __restrict__ Chi,
    __nv_bfloat16* __restrict__ Clo,
    int m0, int n0)
{
    extern __shared__ __align__(128) char smem[];
    const uint32_t sb = smem_u32(smem);
    const int tid = threadIdx.x;
    const int lane = tid & 31, wid = tid >> 5;
    const int wm = (wid >> 2) * 64;     // 2 m-groups
    const int wn = (wid & 3) * 64;      // 4 n-groups of 64

    float c[4][8][4];
#pragma unroll
    for (int i = 0; i < 4; i++)
#pragma unroll
        for (int j = 0; j < 8; j++)
#pragma unroll
            for (int r = 0; r < 4; r++) c[i][j][r] = 0.0f;

    const char* pAh = (const char*)Ahi;
    const char* pAl = (const char*)Alo;
    const char* pBh = (const char*)Bhi;
    const char* pBl = (const char*)Blo;

    auto load_stage = [&](int it) {
        const int k0 = it * 32;
        const uint32_t sbase = sb + (uint32_t)(it % 3) * GSTG;
        // A: 128 rows x 64B hi + lo
#pragma unroll
        for (int t = 0; t < 2; t++) {
            int idx = tid + t * 256;
            int row = idx >> 2;
            int c16 = idx & 3;
            uint32_t sw = (uint32_t)(row * 64 + ((c16 ^ ((row >> 1) & 3)) * 16));
            size_t goA = ((size_t)(m0 + row) * Fd + k0) * 2 + c16 * 16;
            CPA(sbase +    0 + sw, pAh + goA);
            CPA(sbase + 8192 + sw, pAl + goA);
        }
        // B: 256 rows x 64B hi + lo
#pragma unroll
        for (int t = 0; t < 4; t++) {
            int idx = tid + t * 256;
            int row = idx >> 2;
            int c16 = idx & 3;
            uint32_t sw = (uint32_t)(row * 64 + ((c16 ^ ((row >> 1) & 3)) * 16));
            size_t goB = ((size_t)(n0 + row) * Fd + k0) * 2 + c16 * 16;
            CPA(sbase + 16384 + sw, pBh + goB);
            CPA(sbase + 32768 + sw, pBl + goB);
        }
        CPC();
    };

    const int g = lane >> 3, r8 = lane & 7;

    auto compute = [&](uint32_t sbase) {
        const uint32_t abase = sbase;
        const uint32_t bbase = sbase + 16384;
#pragma unroll
        for (int ks = 0; ks < 2; ks++) {
            uint32_t ah[16], al[16];
            const int arow = (g & 1) * 8 + r8;
            const int ac16 = 2 * ks + (g >> 1);
#pragma unroll
            for (int mi = 0; mi < 4; mi++) {
                int r = wm + mi * 16 + arow;
                uint32_t sw = (uint32_t)(r * 64 + ((ac16 ^ ((r >> 1) & 3)) * 16));
                ldsm4(&ah[mi * 4], abase + sw);
                ldsm4(&al[mi * 4], abase + 8192 + sw);
            }
#pragma unroll
            for (int j2 = 0; j2 < 4; j2++) {
                uint32_t bh[4], bl[4];
                int br = wn + (2 * j2 + (g >> 1)) * 8 + r8;
                int bc16 = 2 * ks + (g & 1);
                uint32_t sw = (uint32_t)(br * 64 + ((bc16 ^ ((br >> 1) & 3)) * 16));
                ldsm4(bh, bbase + sw);
                ldsm4(bl, bbase + 16384 + sw);
#pragma unroll
                for (int mi = 0; mi < 4; mi++) {
                    mma16816(c[mi][2*j2],     &ah[mi * 4], bh[0], bh[1]);
                    mma16816(c[mi][2*j2 + 1], &ah[mi * 4], bh[2], bh[3]);
                }
#pragma unroll
                for (int mi = 0; mi < 4; mi++) {
                    mma16816(c[mi][2*j2],     &ah[mi * 4], bl[0], bl[1]);
                    mma16816(c[mi][2*j2 + 1], &ah[mi * 4], bl[2], bl[3]);
                }
#pragma unroll
                for (int mi = 0; mi < 4; mi++) {
                    mma16816(c[mi][2*j2],     &al[mi * 4], bh[0], bh[1]);
                    mma16816(c[mi][2*j2 + 1], &al[mi * 4], bh[2], bh[3]);
                }
            }
        }
    };

    load_stage(0);
    load_stage(1);
    for (int it = 0; it < Fd / 32; it++) {
        CPW1();
        __syncthreads();
        if (it + 2 < Fd / 32) load_stage(it + 2);
        compute(sb + (uint32_t)(it % 3) * GSTG);
    }

    const int crow = lane >> 2;
    const int ccol = (lane & 3) * 2;
#pragma unroll
    for (int mi = 0; mi < 4; mi++) {
#pragma unroll
        for (int nj = 0; nj < 8; nj++) {
            const int m = m0 + wm + mi * 16 + crow;
            const int n = n0 + wn + nj * 8 + ccol;
            const float b0 = __ldg(&bias[n]);
            const float b1 = __ldg(&bias[n + 1]);
            float v00 = (c[mi][nj][0] + b0) * scale;
            float v01 = (c[mi][nj][1] + b1) * scale;
            float v10 = (c[mi][nj][2] + b0) * scale;
            float v11 = (c[mi][nj][3] + b1) * scale;
            if (MODE == 0) {
                float2 o0 = {v00, v01}, o1 = {v10, v11};
                *reinterpret_cast<float2*>(&C[(size_t)m * Fd + n]) = o0;
                *reinterpret_cast<float2*>(&C[(size_t)(m + 8) * Fd + n]) = o1;
            } else {
                const int bb = m >> 10, ss = m & 1023;
                const int hh = n >> 6, dd = n & 63;
                size_t off0 = (((size_t)(bb * Hh + hh)) * Sq + ss) * Dd + dd;
                size_t off1 = off0 + 8 * Dd;
                __nv_bfloat16 h00 = __float2bfloat16(v00);
                __nv_bfloat16 h01 = __float2bfloat16(v01);
                __nv_bfloat16 h10 = __float2bfloat16(v10);
                __nv_bfloat16 h11 = __float2bfloat16(v11);
                __nv_bfloat162 hp0 = __nv_bfloat162(h00, h01);
                __nv_bfloat162 hp1 = __nv_bfloat162(h10, h11);
                __nv_bfloat162 lp0 = __nv_bfloat162(
                    __float2bfloat16(v00 - __bfloat162float(h00)),
                    __float2bfloat16(v01 - __bfloat162float(h01)));
                __nv_bfloat162 lp1 = __nv_bfloat162(
                    __float2bfloat16(v10 - __bfloat162float(h10)),
                    __float2bfloat16(v11 - __bfloat162float(h11)));
                *reinterpret_cast<uint32_t*>(&Chi[off0]) = *reinterpret_cast<uint32_t*>(&hp0);
                *reinterpret_cast<uint32_t*>(&Chi[off1]) = *reinterpret_cast<uint32_t*>(&hp1);
                *reinterpret_cast<uint32_t*>(&Clo[off0]) = *reinterpret_cast<uint32_t*>(&lp0);
                *reinterpret_cast<uint32_t*>(&Clo[off1]) = *reinterpret_cast<uint32_t*>(&lp1);
            }
        }
    }
}

__global__ __launch_bounds__(256) void qkv_gemm(
    const float* __restrict__ bq, const float* __restrict__ bk,
    const float* __restrict__ bv)
{
    const int z = blockIdx.z;
    const float* bias = (z == 0) ? bq : (z == 1) ? bk : bv;
    __nv_bfloat16* Chi = (z == 0) ? g_qh : (z == 1) ? g_kh : g_vh;
    __nv_bfloat16* Clo = (z == 0) ? g_ql : (z == 1) ? g_kl : g_vl;
    const float scale = (z == 0) ? 0.125f : 1.0f;
    gemm_mma<1>(g_xhi, g_xlo,
                g_wthi + (size_t)z * Fd * Fd, g_wtlo + (size_t)z * Fd * Fd,
                bias, scale, nullptr, Chi, Clo,
                blockIdx.y * 128, blockIdx.x * 256);
}

__global__ __launch_bounds__(256) void out_gemm(
    const float* __restrict__ bo, float* __restrict__ out)
{
    gemm_mma<0>(g_yhi, g_ylo,
                g_wthi + (size_t)3 * Fd * Fd, g_wtlo + (size_t)3 * Fd * Fd,
                bo, 1.0f, out, nullptr, nullptr,
                blockIdx.y * 128, blockIdx.x * 256);
}

// ---------------------------------------------------------------------------
// Flash attention (unchanged from R11): no-max softmax, R via __ldg.
// 64 q-rows/CTA, 32-key tiles, bf16 hi/lo Q/K/V. 4 CTAs/SM.
// ---------------------------------------------------------------------------
#define AKH 0
#define AKL 4608
#define AVH 9216
#define AVL 13824
#define ASTG 18432
#define ASMEM (2*ASTG)
#define KVPITCH 144
#define NKT 32

__global__ __launch_bounds__(128, 4) void attn_mma(const float* __restrict__ R)
{
    extern __shared__ __align__(128) char smem[];
    const uint32_t sb = smem_u32(smem);
    const int tid = threadIdx.x;
    const int lane = tid & 31, w = tid >> 5;
    const int bb = blockIdx.x;
    const int hh = blockIdx.y >> 4;
    const int qt = blockIdx.y & 15;
    const int bh = bb * Hh + hh;

    const int lr = lane & 7;
    const int sel8  = (lane & 8) ? 8 : 0;
    const int sel16 = (lane & 16) ? 8 : 0;
    const int crow = lane >> 2;
    const int ct = (lane & 3) * 2;

    const __nv_bfloat16* Kh = g_kh + (size_t)bh * Sq * Dd;
    const __nv_bfloat16* Kl = g_kl + (size_t)bh * Sq * Dd;
    const __nv_bfloat16* Vh = g_vh + (size_t)bh * Sq * Dd;
    const __nv_bfloat16* Vl = g_vl + (size_t)bh * Sq * Dd;
    const int rrow0 = w * 16 + crow;
    const float* Rrow0 = R + (size_t)hh * Sq * Sq + (size_t)(qt * 64 + rrow0) * Sq;
    const float* Rrow1 = Rrow0 + 8 * (size_t)Sq;

    auto load_stage = [&](int stg, int kt) {
        const int k0 = kt * 32;
        const uint32_t sbase = sb + stg * ASTG;
#pragma unroll
        for (int i = 0; i < 2; i++) {
            int idx = tid + i * 128;
            int row = idx >> 3;
            int seg = (idx & 7) * 16;
            uint32_t so = sbase + row * KVPITCH + seg;
            size_t go = ((size_t)(k0 + row)) * Dd + (seg >> 1);
            CPA(so + AKH, Kh + go);
            CPA(so + AKL, Kl + go);
            CPA(so + AVH, Vh + go);
            CPA(so + AVL, Vl + go);
        }
        CPC();
    };

    load_stage(0, 0);
    {
        const uint32_t qbase = sb + ASTG;
        const __nv_bfloat16* Qh = g_qh + ((size_t)bh * Sq + qt * 64) * Dd;
        const __nv_bfloat16* Ql = g_ql + ((size_t)bh * Sq + qt * 64) * Dd;
#pragma unroll
        for (int i = 0; i < 4; i++) {
            int idx = tid + i * 128;
            int row = idx >> 3;
            int seg = (idx & 7) * 16;
            uint32_t so = qbase + row * KVPITCH + seg;
            size_t go = (size_t)row * Dd + (seg >> 1);
            CPA(so, Qh + go);
            CPA(so + 9216, Ql + go);
        }
        CPC();
    }
    CPW0();
    __syncthreads();

    uint32_t qfh[4][4], qfl[4][4];
    {
        const uint32_t qbase = sb + ASTG;
        const int arow = w * 16 + lr + sel8;
#pragma unroll
        for (int cc = 0; cc < 4; cc++) {
            const int acol = cc * 16 + sel16;
            uint32_t ad = qbase + (uint32_t)(arow * KVPITCH + acol * 2);
            ldsm4(qfh[cc], ad);
            ldsm4(qfl[cc], ad + 9216);
        }
    }
    __syncthreads();

    float o[8][4];
#pragma unroll
    for (int j = 0; j < 8; j++)
#pragma unroll
        for (int r = 0; r < 4; r++) o[j][r] = 0.0f;
    float lval0 = 0.0f, lval1 = 0.0f;

    for (int kt = 0; kt < NKT; kt++) {
        if (kt + 1 < NKT) load_stage((kt + 1) & 1, kt + 1);
        const uint32_t stg = sb + (kt & 1) * ASTG;
        const int k0 = kt * 32;

        float2 rv0[4], rv1[4];
#pragma unroll
        for (int j = 0; j < 4; j++) {
            const int cj = k0 + j * 8 + ct;
            rv0[j] = __ldg(reinterpret_cast<const float2*>(Rrow0 + cj));
            rv1[j] = __ldg(reinterpret_cast<const float2*>(Rrow1 + cj));
        }

        float c[4][4];
#pragma unroll
        for (int j = 0; j < 4; j++)
#pragma unroll
            for (int r = 0; r < 4; r++) c[j][r] = 0.0f;

#pragma unroll
        for (int cc = 0; cc < 4; cc++) {
            const int bcol = cc * 16 + sel8;
            uint32_t kh0[4], kl0[4], kh1[4], kl1[4];
            {
                uint32_t kd0 = stg + (uint32_t)((lr + sel16) * KVPITCH + bcol * 2);
                uint32_t kd1 = stg + (uint32_t)((16 + lr + sel16) * KVPITCH + bcol * 2);
                ldsm4(kh0, kd0 + AKH);
                ldsm4(kl0, kd0 + AKL);
                ldsm4(kh1, kd1 + AKH);
                ldsm4(kl1, kd1 + AKL);
            }
            mma16816(c[0], qfh[cc], kh0[0], kh0[1]);
            mma16816(c[1], qfh[cc], kh0[2], kh0[3]);
            mma16816(c[2], qfh[cc], kh1[0], kh1[1]);
            mma16816(c[3], qfh[cc], kh1[2], kh1[3]);
            mma16816(c[0], qfh[cc], kl0[0], kl0[1]);
            mma16816(c[1], qfh[cc], kl0[2], kl0[3]);
            mma16816(c[2], qfh[cc], kl1[0], kl1[1]);
            mma16816(c[3], qfh[cc], kl1[2], kl1[3]);
            mma16816(c[0], qfl[cc], kh0[0], kh0[1]);
            mma16816(c[1], qfl[cc], kh0[2], kh0[3]);
            mma16816(c[2], qfl[cc], kh1[0], kh1[1]);
            mma16816(c[3], qfl[cc], kh1[2], kh1[3]);
        }

        uint32_t pah[2][4], pal[2][4];
#pragma unroll
        for (int j = 0; j < 4; j++) {
            float p00 = __expf(c[j][0] + rv0[j].x);
            float p01 = __expf(c[j][1] + rv0[j].y);
            float p10 = __expf(c[j][2] + rv1[j].x);
            float p11 = __expf(c[j][3] + rv1[j].y);
            lval0 += p00 + p01;
            lval1 += p10 + p11;
            __nv_bfloat16 h00 = __float2bfloat16(p00);
            __nv_bfloat16 h01 = __float2bfloat16(p01);
            __nv_bfloat16 h10 = __float2bfloat16(p10);
            __nv_bfloat16 h11 = __float2bfloat16(p11);
            const int kc = j >> 1, sl = (j & 1) * 2;
            {
                __nv_bfloat162 t0 = __nv_bfloat162(h00, h01);
                __nv_bfloat162 t1 = __nv_bfloat162(h10, h11);
                pah[kc][sl]   = *reinterpret_cast<uint32_t*>(&t0);
                pah[kc][sl+1] = *reinterpret_cast<uint32_t*>(&t1);
            }
            {
                __nv_bfloat162 t0 = __nv_bfloat162(
                    __float2bfloat16(p00 - __bfloat162float(h00)),
                    __float2bfloat16(p01 - __bfloat162float(h01)));
                __nv_bfloat162 t1 = __nv_bfloat162(
                    __float2bfloat16(p10 - __bfloat162float(h10)),
                    __float2bfloat16(p11 - __bfloat162float(h11)));
                pal[kc][sl]   = *reinterpret_cast<uint32_t*>(&t0);
                pal[kc][sl+1] = *reinterpret_cast<uint32_t*>(&t1);
            }
        }

#pragma unroll
        for (int kc = 0; kc < 2; kc++) {
            const int vrow = kc * 16 + lr + sel8;
#pragma unroll
            for (int npp = 0; npp < 4; npp += 2) {
                uint32_t vhA[4], vlA[4], vhB[4], vlB[4];
                uint32_t vdA = stg + (uint32_t)(vrow * KVPITCH + (npp * 16 + sel16) * 2);
                uint32_t vdB = stg + (uint32_t)(vrow * KVPITCH + ((npp + 1) * 16 + sel16) * 2);
                ldsm4t(vhA, vdA + AVH);
                ldsm4t(vlA, vdA + AVL);
                ldsm4t(vhB, vdB + AVH);
                ldsm4t(vlB, vdB + AVL);
                mma16816(o[2*npp],     pah[kc], vhA[0], vhA[1]);
                mma16816(o[2*npp + 1], pah[kc], vhA[2], vhA[3]);
                mma16816(o[2*npp + 2], pah[kc], vhB[0], vhB[1]);
                mma16816(o[2*npp + 3], pah[kc], vhB[2], vhB[3]);
                mma16816(o[2*npp],     pah[kc], vlA[0], vlA[1]);
                mma16816(o[2*npp + 1], pah[kc], vlA[2], vlA[3]);
                mma16816(o[2*npp + 2], pah[kc], vlB[0], vlB[1]);
                mma16816(o[2*npp + 3], pah[kc], vlB[2], vlB[3]);
                mma16816(o[2*npp],     pal[kc], vhA[0], vhA[1]);
                mma16816(o[2*npp + 1], pal[kc], vhA[2], vhA[3]);
                mma16816(o[2*npp + 2], pal[kc], vhB[0], vhB[1]);
                mma16816(o[2*npp + 3], pal[kc], vhB[2], vhB[3]);
            }
        }

        CPW0();
        __syncthreads();
    }

    lval0 += __shfl_xor_sync(0xffffffffu, lval0, 1);
    lval0 += __shfl_xor_sync(0xffffffffu, lval0, 2);
    lval1 += __shfl_xor_sync(0xffffffffu, lval1, 1);
    lval1 += __shfl_xor_sync(0xffffffffu, lval1, 2);
    const float inv0 = 1.0f / lval0;
    const float inv1 = 1.0f / lval1;
    const int row0 = bb * Sq + qt * 64 + w * 16 + crow;
#pragma unroll
    for (int j = 0; j < 8; j++) {
        const int col = hh * Dd + j * 8 + ct;
        float v00 = o[j][0] * inv0, v01 = o[j][1] * inv0;
        float v10 = o[j][2] * inv1, v11 = o[j][3] * inv1;
        __nv_bfloat16 h00 = __float2bfloat16(v00);
        __nv_bfloat16 h01 = __float2bfloat16(v01);
        __nv_bfloat16 h10 = __float2bfloat16(v10);
        __nv_bfloat16 h11 = __float2bfloat16(v11);
        __nv_bfloat162 hp0 = __nv_bfloat162(h00, h01);
        __nv_bfloat162 hp1 = __nv_bfloat162(h10, h11);
        __nv_bfloat162 lp0 = __nv_bfloat162(
            __float2bfloat16(v00 - __bfloat162float(h00)),
            __float2bfloat16(v01 - __bfloat162float(h01)));
        __nv_bfloat162 lp1 = __nv_bfloat162(
            __float2bfloat16(v10 - __bfloat162float(h10)),
            __float2bfloat16(v11 - __bfloat162float(h11)));
        size_t off0 = (size_t)row0 * Fd + col;
        size_t off1 = off0 + 8 * (size_t)Fd;
        *reinterpret_cast<uint32_t*>(&g_yhi[off0]) = *reinterpret_cast<uint32_t*>(&hp0);
        *reinterpret_cast<uint32_t*>(&g_yhi[off1]) = *reinterpret_cast<uint32_t*>(&hp1);
        *reinterpret_cast<uint32_t*>(&g_ylo[off0]) = *reinterpret_cast<uint32_t*>(&lp0);
        *reinterpret_cast<uint32_t*>(&g_ylo[off1]) = *reinterpret_cast<uint32_t*>(&lp1);
    }
}

// ---------------------------------------------------------------------------
extern "C" void kernel_launch(void* const* d_in, const int* in_sizes, int n_in,
                              void* d_out, int out_size)
{
    const float* inputs_q = (const float*)d_in[0];
    const float* Wq = (const float*)d_in[1];
    const float* bq = (const float*)d_in[2];
    const float* Wk = (const float*)d_in[3];
    const float* bk = (const float*)d_in[4];
    const float* Wv = (const float*)d_in[5];
    const float* bv = (const float*)d_in[6];
    const float* R  = (const float*)d_in[7];
    const float* Wo = (const float*)d_in[8];
    const float* bo = (const float*)d_in[9];
    float* out = (float*)d_out;

    cudaFuncSetAttribute(qkv_gemm, cudaFuncAttributeMaxDynamicSharedMemorySize, GSMEM);
    cudaFuncSetAttribute(out_gemm, cudaFuncAttributeMaxDynamicSharedMemorySize, GSMEM);
    cudaFuncSetAttribute(attn_mma, cudaFuncAttributeMaxDynamicSharedMemorySize, ASMEM);

    split_x<<<4096, 256>>>(inputs_q);
    split_wt<<<dim3(32, 32, 4), dim3(32, 8)>>>(Wq, Wk, Wv, Wo);

    qkv_gemm<<<dim3(Fd / 256, (Bsz * Sq) / 128, 3), 256, GSMEM>>>(bq, bk, bv);

    attn_mma<<<dim3(Bsz, Hh * 16), 128, ASMEM>>>(R);

    out_gemm<<<dim3(Fd / 256, (Bsz * Sq) / 128), 256, GSMEM>>>(bo, out);
}

// round 13
// speedup vs baseline: 1.4759x; 1.4759x over previous
#include <cuda_runtime.h>
#include <cuda_bf16.h>
#include <math.h>
#include <stdint.h>

#define Bsz 4
#define Sq  1024
#define Fd  1024
#define Hh  16
#define Dd  64

// ---------------------------------------------------------------------------
// Scratch (device globals)
// ---------------------------------------------------------------------------
__device__ __nv_bfloat16 g_xhi[Bsz*Sq*Fd];
__device__ __nv_bfloat16 g_xlo[Bsz*Sq*Fd];
__device__ __nv_bfloat16 g_wthi[4*Fd*Fd];   // [N][K] x4 (Wq,Wk,Wv,Wo)
__device__ __nv_bfloat16 g_wtlo[4*Fd*Fd];
__device__ __nv_bfloat16 g_qh[Bsz*Hh*Sq*Dd];
__device__ __nv_bfloat16 g_ql[Bsz*Hh*Sq*Dd];
__device__ __nv_bfloat16 g_kh[Bsz*Hh*Sq*Dd];
__device__ __nv_bfloat16 g_kl[Bsz*Hh*Sq*Dd];
__device__ __nv_bfloat16 g_vh[Bsz*Hh*Sq*Dd];
__device__ __nv_bfloat16 g_vl[Bsz*Hh*Sq*Dd];
__device__ __nv_bfloat16 g_yhi[Bsz*Sq*Fd];
__device__ __nv_bfloat16 g_ylo[Bsz*Sq*Fd];

// ---------------------------------------------------------------------------
// PTX helpers (baseline PTX only)
// ---------------------------------------------------------------------------
__device__ __forceinline__ uint32_t smem_u32(const void* p) {
    uint32_t a;
    asm("{ .reg .u64 t; cvta.to.shared.u64 t, %1; cvt.u32.u64 %0, t; }"
        : "=r"(a) : "l"(p));
    return a;
}

#define CPA(dst, src) do {                                                   \
    uint64_t _g = __cvta_generic_to_global((const void*)(src));              \
    asm volatile("cp.async.ca.shared.global [%0], [%1], 16;"                 \
                 :: "r"(dst), "l"(_g) : "memory");                           \
} while (0)
#define CPC() asm volatile("cp.async.commit_group;" ::: "memory")
#define CPW0() asm volatile("cp.async.wait_group 0;" ::: "memory")
#define CPW1() asm volatile("cp.async.wait_group 1;" ::: "memory")

__device__ __forceinline__ void ldsm4(uint32_t r[4], uint32_t addr) {
    asm volatile("ldmatrix.sync.aligned.m8n8.x4.shared.b16 {%0,%1,%2,%3}, [%4];"
        : "=r"(r[0]), "=r"(r[1]), "=r"(r[2]), "=r"(r[3]) : "r"(addr));
}
__device__ __forceinline__ void ldsm4t(uint32_t r[4], uint32_t addr) {
    asm volatile("ldmatrix.sync.aligned.m8n8.x4.trans.shared.b16 {%0,%1,%2,%3}, [%4];"
        : "=r"(r[0]), "=r"(r[1]), "=r"(r[2]), "=r"(r[3]) : "r"(addr));
}

__device__ __forceinline__ void mma16816(float* c, const uint32_t* a,
                                         uint32_t b0, uint32_t b1) {
    asm volatile("mma.sync.aligned.m16n8k16.row.col.f32.bf16.bf16.f32 "
        "{%0,%1,%2,%3}, {%4,%5,%6,%7}, {%8,%9}, {%0,%1,%2,%3};"
        : "+f"(c[0]), "+f"(c[1]), "+f"(c[2]), "+f"(c[3])
        : "r"(a[0]), "r"(a[1]), "r"(a[2]), "r"(a[3]), "r"(b0), "r"(b1));
}

// ---------------------------------------------------------------------------
// Conversions
// ---------------------------------------------------------------------------
__global__ void split_x(const float* __restrict__ X) {
    int i = (blockIdx.x * blockDim.x + threadIdx.x) * 4;
    float4 v = *reinterpret_cast<const float4*>(&X[i]);
    float vv[4] = {v.x, v.y, v.z, v.w};
#pragma unroll
    for (int j = 0; j < 4; j++) {
        __nv_bfloat16 h = __float2bfloat16(vv[j]);
        g_xhi[i + j] = h;
        g_xlo[i + j] = __float2bfloat16(vv[j] - __bfloat162float(h));
    }
}

__global__ void split_wt(const float* __restrict__ Wq, const float* __restrict__ Wk,
                         const float* __restrict__ Wv, const float* __restrict__ Wo) {
    __shared__ float t[32][33];
    const int z = blockIdx.z;
    const float* __restrict__ W = (z == 0) ? Wq : (z == 1) ? Wk : (z == 2) ? Wv : Wo;
    __nv_bfloat16* hi = g_wthi + (size_t)z * Fd * Fd;
    __nv_bfloat16* lo = g_wtlo + (size_t)z * Fd * Fd;

    const int tx = threadIdx.x, ty = threadIdx.y;
    const int kbase = blockIdx.y * 32, nbase = blockIdx.x * 32;
#pragma unroll
    for (int i = 0; i < 4; i++) {
        int kr = ty * 4 + i;
        t[kr][tx] = W[(size_t)(kbase + kr) * Fd + nbase + tx];
    }
    __syncthreads();
#pragma unroll
    for (int i = 0; i < 4; i++) {
        int nr = ty * 4 + i;
        float v = t[tx][nr];
        __nv_bfloat16 h = __float2bfloat16(v);
        size_t o = (size_t)(nbase + nr) * Fd + kbase + tx;
        hi[o] = h;
        lo[o] = __float2bfloat16(v - __bfloat162float(h));
    }
}

// ---------------------------------------------------------------------------
// mma.sync GEMM: bf16 3-term hi/lo, 3-stage cp.async ring, XOR-swizzled smem.
// BM=128, BN=128, BK=32, 8 warps (2m x 4n), warp tile 64x32. (R8 config)
// ---------------------------------------------------------------------------
#define GSTG  32768
#define GSMEM (3*GSTG)

template<int MODE>
__device__ __forceinline__ void gemm_mma(
    const __nv_bfloat16* __restrict__ Ahi, const __nv_bfloat16* __restrict__ Alo,
    const __nv_bfloat16* __restrict__ Bhi, const __nv_bfloat16* __restrict__ Blo,
    const float* __restrict__ bias, float scale,
    float* __restrict__ C, __nv_bfloat16* __restrict__ Chi,
    __nv_bfloat16* __restrict__ Clo,
    int m0, int n0)
{
    extern __shared__ __align__(128) char smem[];
    const uint32_t sb = smem_u32(smem);
    const int tid = threadIdx.x;
    const int lane = tid & 31, wid = tid >> 5;
    const int wm = (wid >> 2) * 64;
    const int wn = (wid & 3) * 32;

    float c[4][4][4];
#pragma unroll
    for (int i = 0; i < 4; i++)
#pragma unroll
        for (int j = 0; j < 4; j++)
#pragma unroll
            for (int r = 0; r < 4; r++) c[i][j][r] = 0.0f;

    const char* pAh = (const char*)Ahi;
    const char* pAl = (const char*)Alo;
    const char* pBh = (const char*)Bhi;
    const char* pBl = (const char*)Blo;

    auto load_stage = [&](int it) {
        const int k0 = it * 32;
        const uint32_t sbase = sb + (uint32_t)(it % 3) * GSTG;
#pragma unroll
        for (int t = 0; t < 2; t++) {
            int idx = tid + t * 256;
            int row = idx >> 2;
            int c16 = idx & 3;
            uint32_t sw = (uint32_t)(row * 64 + ((c16 ^ ((row >> 1) & 3)) * 16));
            size_t goA = ((size_t)(m0 + row) * Fd + k0) * 2 + c16 * 16;
            size_t goB = ((size_t)(n0 + row) * Fd + k0) * 2 + c16 * 16;
            CPA(sbase +     0 + sw, pAh + goA);
            CPA(sbase +  8192 + sw, pAl + goA);
            CPA(sbase + 16384 + sw, pBh + goB);
            CPA(sbase + 24576 + sw, pBl + goB);
        }
        CPC();
    };

    const int g = lane >> 3, r8 = lane & 7;

    auto compute = [&](uint32_t sbase) {
        const uint32_t abase = sbase;
        const uint32_t bbase = sbase + 16384;
#pragma unroll
        for (int ks = 0; ks < 2; ks++) {
            uint32_t ah[16], al[16];
            const int arow = (g & 1) * 8 + r8;
            const int ac16 = 2 * ks + (g >> 1);
#pragma unroll
            for (int mi = 0; mi < 4; mi++) {
                int r = wm + mi * 16 + arow;
                uint32_t sw = (uint32_t)(r * 64 + ((ac16 ^ ((r >> 1) & 3)) * 16));
                ldsm4(&ah[mi * 4], abase + sw);
                ldsm4(&al[mi * 4], abase + 8192 + sw);
            }
#pragma unroll
            for (int j2 = 0; j2 < 2; j2++) {
                uint32_t bh[4], bl[4];
                int br = wn + (2 * j2 + (g >> 1)) * 8 + r8;
                int bc16 = 2 * ks + (g & 1);
                uint32_t sw = (uint32_t)(br * 64 + ((bc16 ^ ((br >> 1) & 3)) * 16));
                ldsm4(bh, bbase + sw);
                ldsm4(bl, bbase + 8192 + sw);
#pragma unroll
                for (int mi = 0; mi < 4; mi++) {
                    mma16816(c[mi][2*j2],     &ah[mi * 4], bh[0], bh[1]);
                    mma16816(c[mi][2*j2 + 1], &ah[mi * 4], bh[2], bh[3]);
                }
#pragma unroll
                for (int mi = 0; mi < 4; mi++) {
                    mma16816(c[mi][2*j2],     &ah[mi * 4], bl[0], bl[1]);
                    mma16816(c[mi][2*j2 + 1], &ah[mi * 4], bl[2], bl[3]);
                }
#pragma unroll
                for (int mi = 0; mi < 4; mi++) {
                    mma16816(c[mi][2*j2],     &al[mi * 4], bh[0], bh[1]);
                    mma16816(c[mi][2*j2 + 1], &al[mi * 4], bh[2], bh[3]);
                }
            }
        }
    };

    load_stage(0);
    load_stage(1);
    for (int it = 0; it < Fd / 32; it++) {
        CPW1();
        __syncthreads();
        if (it + 2 < Fd / 32) load_stage(it + 2);
        compute(sb + (uint32_t)(it % 3) * GSTG);
    }

    const int crow = lane >> 2;
    const int ccol = (lane & 3) * 2;
#pragma unroll
    for (int mi = 0; mi < 4; mi++) {
#pragma unroll
        for (int nj = 0; nj < 4; nj++) {
            const int m = m0 + wm + mi * 16 + crow;
            const int n = n0 + wn + nj * 8 + ccol;
            const float b0 = __ldg(&bias[n]);
            const float b1 = __ldg(&bias[n + 1]);
            float v00 = (c[mi][nj][0] + b0) * scale;
            float v01 = (c[mi][nj][1] + b1) * scale;
            float v10 = (c[mi][nj][2] + b0) * scale;
            float v11 = (c[mi][nj][3] + b1) * scale;
            if (MODE == 0) {
                float2 o0 = {v00, v01}, o1 = {v10, v11};
                *reinterpret_cast<float2*>(&C[(size_t)m * Fd + n]) = o0;
                *reinterpret_cast<float2*>(&C[(size_t)(m + 8) * Fd + n]) = o1;
            } else {
                const int bb = m >> 10, ss = m & 1023;
                const int hh = n >> 6, dd = n & 63;
                size_t off0 = (((size_t)(bb * Hh + hh)) * Sq + ss) * Dd + dd;
                size_t off1 = off0 + 8 * Dd;
                __nv_bfloat16 h00 = __float2bfloat16(v00);
                __nv_bfloat16 h01 = __float2bfloat16(v01);
                __nv_bfloat16 h10 = __float2bfloat16(v10);
                __nv_bfloat16 h11 = __float2bfloat16(v11);
                __nv_bfloat162 hp0 = __nv_bfloat162(h00, h01);
                __nv_bfloat162 hp1 = __nv_bfloat162(h10, h11);
                __nv_bfloat162 lp0 = __nv_bfloat162(
                    __float2bfloat16(v00 - __bfloat162float(h00)),
                    __float2bfloat16(v01 - __bfloat162float(h01)));
                __nv_bfloat162 lp1 = __nv_bfloat162(
                    __float2bfloat16(v10 - __bfloat162float(h10)),
                    __float2bfloat16(v11 - __bfloat162float(h11)));
                *reinterpret_cast<uint32_t*>(&Chi[off0]) = *reinterpret_cast<uint32_t*>(&hp0);
                *reinterpret_cast<uint32_t*>(&Chi[off1]) = *reinterpret_cast<uint32_t*>(&hp1);
                *reinterpret_cast<uint32_t*>(&Clo[off0]) = *reinterpret_cast<uint32_t*>(&lp0);
                *reinterpret_cast<uint32_t*>(&Clo[off1]) = *reinterpret_cast<uint32_t*>(&lp1);
            }
        }
    }
}

__global__ __launch_bounds__(256, 2) void qkv_gemm(
    const float* __restrict__ bq, const float* __restrict__ bk,
    const float* __restrict__ bv)
{
    const int z = blockIdx.z;
    const float* bias = (z == 0) ? bq : (z == 1) ? bk : bv;
    __nv_bfloat16* Chi = (z == 0) ? g_qh : (z == 1) ? g_kh : g_vh;
    __nv_bfloat16* Clo = (z == 0) ? g_ql : (z == 1) ? g_kl : g_vl;
    const float scale = (z == 0) ? 0.125f : 1.0f;
    gemm_mma<1>(g_xhi, g_xlo,
                g_wthi + (size_t)z * Fd * Fd, g_wtlo + (size_t)z * Fd * Fd,
                bias, scale, nullptr, Chi, Clo,
                blockIdx.y * 128, blockIdx.x * 128);
}

__global__ __launch_bounds__(256, 2) void out_gemm(
    const float* __restrict__ bo, float* __restrict__ out)
{
    gemm_mma<0>(g_yhi, g_ylo,
                g_wthi + (size_t)3 * Fd * Fd, g_wtlo + (size_t)3 * Fd * Fd,
                bo, 1.0f, out, nullptr, nullptr,
                blockIdx.y * 128, blockIdx.x * 128);
}

// ---------------------------------------------------------------------------
// Flash attention: no-max softmax, R via __ldg, 3-stage K/V cp.async ring
// with wait_group 1 (prefetch 2 tiles ahead). 64 q-rows/CTA, 4 CTAs/SM.
// smem: 3 stages x 18432 = 55296 B.
// ---------------------------------------------------------------------------
#define AKH 0
#define AKL 4608
#define AVH 9216
#define AVL 13824
#define ASTG 18432
#define ASMEM (3*ASTG)
#define KVPITCH 144
#define NKT 32

__global__ __launch_bounds__(128, 4) void attn_mma(const float* __restrict__ R)
{
    extern __shared__ __align__(128) char smem[];
    const uint32_t sb = smem_u32(smem);
    const int tid = threadIdx.x;
    const int lane = tid & 31, w = tid >> 5;
    const int bb = blockIdx.x;
    const int hh = blockIdx.y >> 4;
    const int qt = blockIdx.y & 15;
    const int bh = bb * Hh + hh;

    const int lr = lane & 7;
    const int sel8  = (lane & 8) ? 8 : 0;
    const int sel16 = (lane & 16) ? 8 : 0;
    const int crow = lane >> 2;
    const int ct = (lane & 3) * 2;

    const __nv_bfloat16* Kh = g_kh + (size_t)bh * Sq * Dd;
    const __nv_bfloat16* Kl = g_kl + (size_t)bh * Sq * Dd;
    const __nv_bfloat16* Vh = g_vh + (size_t)bh * Sq * Dd;
    const __nv_bfloat16* Vl = g_vl + (size_t)bh * Sq * Dd;
    const int rrow0 = w * 16 + crow;
    const float* Rrow0 = R + (size_t)hh * Sq * Sq + (size_t)(qt * 64 + rrow0) * Sq;
    const float* Rrow1 = Rrow0 + 8 * (size_t)Sq;

    auto load_stage = [&](int kt) {
        const int k0 = kt * 32;
        const uint32_t sbase = sb + (uint32_t)(kt % 3) * ASTG;
#pragma unroll
        for (int i = 0; i < 2; i++) {
            int idx = tid + i * 128;
            int row = idx >> 3;
            int seg = (idx & 7) * 16;
            uint32_t so = sbase + row * KVPITCH + seg;
            size_t go = ((size_t)(k0 + row)) * Dd + (seg >> 1);
            CPA(so + AKH, Kh + go);
            CPA(so + AKL, Kl + go);
            CPA(so + AVH, Vh + go);
            CPA(so + AVL, Vl + go);
        }
        CPC();
    };

    // ---- Q fragments: stage via stage-2 buffer (overwritten later; safe
    //      because stage 2 is first written by load_stage(2) AFTER this read)
    {
        const uint32_t qbase = sb + 2 * ASTG;
        const __nv_bfloat16* Qh = g_qh + ((size_t)bh * Sq + qt * 64) * Dd;
        const __nv_bfloat16* Ql = g_ql + ((size_t)bh * Sq + qt * 64) * Dd;
#pragma unroll
        for (int i = 0; i < 4; i++) {
            int idx = tid + i * 128;
            int row = idx >> 3;
            int seg = (idx & 7) * 16;
            uint32_t so = qbase + row * KVPITCH + seg;
            size_t go = (size_t)row * Dd + (seg >> 1);
            CPA(so, Qh + go);
            CPA(so + 9216, Ql + go);
        }
        CPC();
    }
    CPW0();
    __syncthreads();

    uint32_t qfh[4][4], qfl[4][4];
    {
        const uint32_t qbase = sb + 2 * ASTG;
        const int arow = w * 16 + lr + sel8;
#pragma unroll
        for (int cc = 0; cc < 4; cc++) {
            const int acol = cc * 16 + sel16;
            uint32_t ad = qbase + (uint32_t)(arow * KVPITCH + acol * 2);
            ldsm4(qfh[cc], ad);
            ldsm4(qfl[cc], ad + 9216);
        }
    }
    __syncthreads();

    // ---- prime the 2-deep K/V pipeline ----
    load_stage(0);
    load_stage(1);

    float o[8][4];
#pragma unroll
    for (int j = 0; j < 8; j++)
#pragma unroll
        for (int r = 0; r < 4; r++) o[j][r] = 0.0f;
    float lval0 = 0.0f, lval1 = 0.0f;

    for (int kt = 0; kt < NKT; kt++) {
        CPW1();               // stage kt complete (<=1 newer group pending)
        __syncthreads();      // all warps done reading stage (kt+2)%3's old data
        if (kt + 2 < NKT) load_stage(kt + 2);
        const uint32_t stg = sb + (uint32_t)(kt % 3) * ASTG;
        const int k0 = kt * 32;

        // ---- prefetch R via LDG (hidden under QK MMAs) ----
        float2 rv0[4], rv1[4];
#pragma unroll
        for (int j = 0; j < 4; j++) {
            const int cj = k0 + j * 8 + ct;
            rv0[j] = __ldg(reinterpret_cast<const float2*>(Rrow0 + cj));
            rv1[j] = __ldg(reinterpret_cast<const float2*>(Rrow1 + cj));
        }

        // ---- QK^T (3-term hi/lo) ----
        float c[4][4];
#pragma unroll
        for (int j = 0; j < 4; j++)
#pragma unroll
            for (int r = 0; r < 4; r++) c[j][r] = 0.0f;

#pragma unroll
        for (int cc = 0; cc < 4; cc++) {
            const int bcol = cc * 16 + sel8;
            uint32_t kh0[4], kl0[4], kh1[4], kl1[4];
            {
                uint32_t kd0 = stg + (uint32_t)((lr + sel16) * KVPITCH + bcol * 2);
                uint32_t kd1 = stg + (uint32_t)((16 + lr + sel16) * KVPITCH + bcol * 2);
                ldsm4(kh0, kd0 + AKH);
                ldsm4(kl0, kd0 + AKL);
                ldsm4(kh1, kd1 + AKH);
                ldsm4(kl1, kd1 + AKL);
            }
            mma16816(c[0], qfh[cc], kh0[0], kh0[1]);
            mma16816(c[1], qfh[cc], kh0[2], kh0[3]);
            mma16816(c[2], qfh[cc], kh1[0], kh1[1]);
            mma16816(c[3], qfh[cc], kh1[2], kh1[3]);
            mma16816(c[0], qfh[cc], kl0[0], kl0[1]);
            mma16816(c[1], qfh[cc], kl0[2], kl0[3]);
            mma16816(c[2], qfh[cc], kl1[0], kl1[1]);
            mma16816(c[3], qfh[cc], kl1[2], kl1[3]);
            mma16816(c[0], qfl[cc], kh0[0], kh0[1]);
            mma16816(c[1], qfl[cc], kh0[2], kh0[3]);
            mma16816(c[2], qfl[cc], kh1[0], kh1[1]);
            mma16816(c[3], qfl[cc], kh1[2], kh1[3]);
        }

        // ---- add R, exp (no max shift — scores bounded), split P ----
        uint32_t pah[2][4], pal[2][4];
#pragma unroll
        for (int j = 0; j < 4; j++) {
            float p00 = __expf(c[j][0] + rv0[j].x);
            float p01 = __expf(c[j][1] + rv0[j].y);
            float p10 = __expf(c[j][2] + rv1[j].x);
            float p11 = __expf(c[j][3] + rv1[j].y);
            lval0 += p00 + p01;
            lval1 += p10 + p11;
            __nv_bfloat16 h00 = __float2bfloat16(p00);
            __nv_bfloat16 h01 = __float2bfloat16(p01);
            __nv_bfloat16 h10 = __float2bfloat16(p10);
            __nv_bfloat16 h11 = __float2bfloat16(p11);
            const int kc = j >> 1, sl = (j & 1) * 2;
            {
                __nv_bfloat162 t0 = __nv_bfloat162(h00, h01);
                __nv_bfloat162 t1 = __nv_bfloat162(h10, h11);
                pah[kc][sl]   = *reinterpret_cast<uint32_t*>(&t0);
                pah[kc][sl+1] = *reinterpret_cast<uint32_t*>(&t1);
            }
            {
                __nv_bfloat162 t0 = __nv_bfloat162(
                    __float2bfloat16(p00 - __bfloat162float(h00)),
                    __float2bfloat16(p01 - __bfloat162float(h01)));
                __nv_bfloat162 t1 = __nv_bfloat162(
                    __float2bfloat16(p10 - __bfloat162float(h10)),
                    __float2bfloat16(p11 - __bfloat162float(h11)));
                pal[kc][sl]   = *reinterpret_cast<uint32_t*>(&t0);
                pal[kc][sl+1] = *reinterpret_cast<uint32_t*>(&t1);
            }
        }

        // ---- P @ V (3-term hi/lo) ----
#pragma unroll
        for (int kc = 0; kc < 2; kc++) {
            const int vrow = kc * 16 + lr + sel8;
#pragma unroll
            for (int npp = 0; npp < 4; npp += 2) {
                uint32_t vhA[4], vlA[4], vhB[4], vlB[4];
                uint32_t vdA = stg + (uint32_t)(vrow * KVPITCH + (npp * 16 + sel16) * 2);
                uint32_t vdB = stg + (uint32_t)(vrow * KVPITCH + ((npp + 1) * 16 + sel16) * 2);
                ldsm4t(vhA, vdA + AVH);
                ldsm4t(vlA, vdA + AVL);
                ldsm4t(vhB, vdB + AVH);
                ldsm4t(vlB, vdB + AVL);
                mma16816(o[2*npp],     pah[kc], vhA[0], vhA[1]);
                mma16816(o[2*npp + 1], pah[kc], vhA[2], vhA[3]);
                mma16816(o[2*npp + 2], pah[kc], vhB[0], vhB[1]);
                mma16816(o[2*npp + 3], pah[kc], vhB[2], vhB[3]);
                mma16816(o[2*npp],     pah[kc], vlA[0], vlA[1]);
                mma16816(o[2*npp + 1], pah[kc], vlA[2], vlA[3]);
                mma16816(o[2*npp + 2], pah[kc], vlB[0], vlB[1]);
                mma16816(o[2*npp + 3], pah[kc], vlB[2], vlB[3]);
                mma16816(o[2*npp],     pal[kc], vhA[0], vhA[1]);
                mma16816(o[2*npp + 1], pal[kc], vhA[2], vhA[3]);
                mma16816(o[2*npp + 2], pal[kc], vhB[0], vhB[1]);
                mma16816(o[2*npp + 3], pal[kc], vhB[2], vhB[3]);
            }
        }
    }

    // ---- single cross-lane reduction of l, normalize, write ----
    lval0 += __shfl_xor_sync(0xffffffffu, lval0, 1);
    lval0 += __shfl_xor_sync(0xffffffffu, lval0, 2);
    lval1 += __shfl_xor_sync(0xffffffffu, lval1, 1);
    lval1 += __shfl_xor_sync(0xffffffffu, lval1, 2);
    const float inv0 = 1.0f / lval0;
    const float inv1 = 1.0f / lval1;
    const int row0 = bb * Sq + qt * 64 + w * 16 + crow;
#pragma unroll
    for (int j = 0; j < 8; j++) {
        const int col = hh * Dd + j * 8 + ct;
        float v00 = o[j][0] * inv0, v01 = o[j][1] * inv0;
        float v10 = o[j][2] * inv1, v11 = o[j][3] * inv1;
        __nv_bfloat16 h00 = __float2bfloat16(v00);
        __nv_bfloat16 h01 = __float2bfloat16(v01);
        __nv_bfloat16 h10 = __float2bfloat16(v10);
        __nv_bfloat16 h11 = __float2bfloat16(v11);
        __nv_bfloat162 hp0 = __nv_bfloat162(h00, h01);
        __nv_bfloat162 hp1 = __nv_bfloat162(h10, h11);
        __nv_bfloat162 lp0 = __nv_bfloat162(
            __float2bfloat16(v00 - __bfloat162float(h00)),
            __float2bfloat16(v01 - __bfloat162float(h01)));
        __nv_bfloat162 lp1 = __nv_bfloat162(
            __float2bfloat16(v10 - __bfloat162float(h10)),
            __float2bfloat16(v11 - __bfloat162float(h11)));
        size_t off0 = (size_t)row0 * Fd + col;
        size_t off1 = off0 + 8 * (size_t)Fd;
        *reinterpret_cast<uint32_t*>(&g_yhi[off0]) = *reinterpret_cast<uint32_t*>(&hp0);
        *reinterpret_cast<uint32_t*>(&g_yhi[off1]) = *reinterpret_cast<uint32_t*>(&hp1);
        *reinterpret_cast<uint32_t*>(&g_ylo[off0]) = *reinterpret_cast<uint32_t*>(&lp0);
        *reinterpret_cast<uint32_t*>(&g_ylo[off1]) = *reinterpret_cast<uint32_t*>(&lp1);
    }
}

// ---------------------------------------------------------------------------
extern "C" void kernel_launch(void* const* d_in, const int* in_sizes, int n_in,
                              void* d_out, int out_size)
{
    const float* inputs_q = (const float*)d_in[0];
    const float* Wq = (const float*)d_in[1];
    const float* bq = (const float*)d_in[2];
    const float* Wk = (const float*)d_in[3];
    const float* bk = (const float*)d_in[4];
    const float* Wv = (const float*)d_in[5];
    const float* bv = (const float*)d_in[6];
    const float* R  = (const float*)d_in[7];
    const float* Wo = (const float*)d_in[8];
    const float* bo = (const float*)d_in[9];
    float* out = (float*)d_out;

    cudaFuncSetAttribute(qkv_gemm, cudaFuncAttributeMaxDynamicSharedMemorySize, GSMEM);
    cudaFuncSetAttribute(out_gemm, cudaFuncAttributeMaxDynamicSharedMemorySize, GSMEM);
    cudaFuncSetAttribute(attn_mma, cudaFuncAttributeMaxDynamicSharedMemorySize, ASMEM);

    split_x<<<4096, 256>>>(inputs_q);
    split_wt<<<dim3(32, 32, 4), dim3(32, 8)>>>(Wq, Wk, Wv, Wo);

    qkv_gemm<<<dim3(Fd / 128, (Bsz * Sq) / 128, 3), 256, GSMEM>>>(bq, bk, bv);

    attn_mma<<<dim3(Bsz, Hh * 16), 128, ASMEM>>>(R);

    out_gemm<<<dim3(Fd / 128, (Bsz * Sq) / 128), 256, GSMEM>>>(bo, out);
}

// round 14
// speedup vs baseline: 1.6489x; 1.1173x over previous
#include <cuda_runtime.h>
#include <cuda_bf16.h>
#include <math.h>
#include <stdint.h>

#define Bsz 4
#define Sq  1024
#define Fd  1024
#define Hh  16
#define Dd  64

// ---------------------------------------------------------------------------
// Scratch (device globals)
// ---------------------------------------------------------------------------
__device__ __nv_bfloat16 g_xhi[Bsz*Sq*Fd];
__device__ __nv_bfloat16 g_xlo[Bsz*Sq*Fd];
__device__ __nv_bfloat16 g_wthi[4*Fd*Fd];   // [N][K] x4 (Wq,Wk,Wv,Wo)
__device__ __nv_bfloat16 g_wtlo[4*Fd*Fd];
__device__ __nv_bfloat16 g_qh[Bsz*Hh*Sq*Dd];
__device__ __nv_bfloat16 g_ql[Bsz*Hh*Sq*Dd];
__device__ __nv_bfloat16 g_kh[Bsz*Hh*Sq*Dd];   // K single bf16 (softmax damps K error)
__device__ __nv_bfloat16 g_vh[Bsz*Hh*Sq*Dd];
__device__ __nv_bfloat16 g_vl[Bsz*Hh*Sq*Dd];
__device__ __nv_bfloat16 g_yhi[Bsz*Sq*Fd];
__device__ __nv_bfloat16 g_ylo[Bsz*Sq*Fd];

// ---------------------------------------------------------------------------
// PTX helpers (baseline PTX only)
// ---------------------------------------------------------------------------
__device__ __forceinline__ uint32_t smem_u32(const void* p) {
    uint32_t a;
    asm("{ .reg .u64 t; cvta.to.shared.u64 t, %1; cvt.u32.u64 %0, t; }"
        : "=r"(a) : "l"(p));
    return a;
}

#define CPA(dst, src) do {                                                   \
    uint64_t _g = __cvta_generic_to_global((const void*)(src));              \
    asm volatile("cp.async.ca.shared.global [%0], [%1], 16;"                 \
                 :: "r"(dst), "l"(_g) : "memory");                           \
} while (0)
#define CPC() asm volatile("cp.async.commit_group;" ::: "memory")
#define CPW0() asm volatile("cp.async.wait_group 0;" ::: "memory")
#define CPW1() asm volatile("cp.async.wait_group 1;" ::: "memory")

__device__ __forceinline__ void ldsm4(uint32_t r[4], uint32_t addr) {
    asm volatile("ldmatrix.sync.aligned.m8n8.x4.shared.b16 {%0,%1,%2,%3}, [%4];"
        : "=r"(r[0]), "=r"(r[1]), "=r"(r[2]), "=r"(r[3]) : "r"(addr));
}
__device__ __forceinline__ void ldsm4t(uint32_t r[4], uint32_t addr) {
    asm volatile("ldmatrix.sync.aligned.m8n8.x4.trans.shared.b16 {%0,%1,%2,%3}, [%4];"
        : "=r"(r[0]), "=r"(r[1]), "=r"(r[2]), "=r"(r[3]) : "r"(addr));
}

__device__ __forceinline__ void mma16816(float* c, const uint32_t* a,
                                         uint32_t b0, uint32_t b1) {
    asm volatile("mma.sync.aligned.m16n8k16.row.col.f32.bf16.bf16.f32 "
        "{%0,%1,%2,%3}, {%4,%5,%6,%7}, {%8,%9}, {%0,%1,%2,%3};"
        : "+f"(c[0]), "+f"(c[1]), "+f"(c[2]), "+f"(c[3])
        : "r"(a[0]), "r"(a[1]), "r"(a[2]), "r"(a[3]), "r"(b0), "r"(b1));
}

// ---------------------------------------------------------------------------
// Conversions
// ---------------------------------------------------------------------------
__global__ void split_x(const float* __restrict__ X) {
    int i = (blockIdx.x * blockDim.x + threadIdx.x) * 4;
    float4 v = *reinterpret_cast<const float4*>(&X[i]);
    float vv[4] = {v.x, v.y, v.z, v.w};
#pragma unroll
    for (int j = 0; j < 4; j++) {
        __nv_bfloat16 h = __float2bfloat16(vv[j]);
        g_xhi[i + j] = h;
        g_xlo[i + j] = __float2bfloat16(vv[j] - __bfloat162float(h));
    }
}

__global__ void split_wt(const float* __restrict__ Wq, const float* __restrict__ Wk,
                         const float* __restrict__ Wv, const float* __restrict__ Wo) {
    __shared__ float t[32][33];
    const int z = blockIdx.z;
    const float* __restrict__ W = (z == 0) ? Wq : (z == 1) ? Wk : (z == 2) ? Wv : Wo;
    __nv_bfloat16* hi = g_wthi + (size_t)z * Fd * Fd;
    __nv_bfloat16* lo = g_wtlo + (size_t)z * Fd * Fd;

    const int tx = threadIdx.x, ty = threadIdx.y;
    const int kbase = blockIdx.y * 32, nbase = blockIdx.x * 32;
#pragma unroll
    for (int i = 0; i < 4; i++) {
        int kr = ty * 4 + i;
        t[kr][tx] = W[(size_t)(kbase + kr) * Fd + nbase + tx];
    }
    __syncthreads();
#pragma unroll
    for (int i = 0; i < 4; i++) {
        int nr = ty * 4 + i;
        float v = t[tx][nr];
        __nv_bfloat16 h = __float2bfloat16(v);
        size_t o = (size_t)(nbase + nr) * Fd + kbase + tx;
        hi[o] = h;
        lo[o] = __float2bfloat16(v - __bfloat162float(h));
    }
}

// ---------------------------------------------------------------------------
// mma.sync GEMM: bf16 3-term hi/lo, 3-stage cp.async ring, XOR-swizzled smem.
// BM=128, BN=128, BK=32, 8 warps (2m x 4n), warp tile 64x32. (R8 config)
// MODE: 0 = fp32 C + bias. 1 = hi/lo bf16 [B,H,S,D]. 2 = hi-only bf16 [B,H,S,D].
// ---------------------------------------------------------------------------
#define GSTG  32768
#define GSMEM (3*GSTG)

template<int MODE>
__device__ __forceinline__ void gemm_mma(
    const __nv_bfloat16* __restrict__ Ahi, const __nv_bfloat16* __restrict__ Alo,
    const __nv_bfloat16* __restrict__ Bhi, const __nv_bfloat16* __restrict__ Blo,
    const float* __restrict__ bias, float scale,
    float* __restrict__ C, __nv_bfloat16* __restrict__ Chi,
    __nv_bfloat16* __restrict__ Clo,
    int m0, int n0)
{
    extern __shared__ __align__(128) char smem[];
    const uint32_t sb = smem_u32(smem);
    const int tid = threadIdx.x;
    const int lane = tid & 31, wid = tid >> 5;
    const int wm = (wid >> 2) * 64;
    const int wn = (wid & 3) * 32;

    float c[4][4][4];
#pragma unroll
    for (int i = 0; i < 4; i++)
#pragma unroll
        for (int j = 0; j < 4; j++)
#pragma unroll
            for (int r = 0; r < 4; r++) c[i][j][r] = 0.0f;

    const char* pAh = (const char*)Ahi;
    const char* pAl = (const char*)Alo;
    const char* pBh = (const char*)Bhi;
    const char* pBl = (const char*)Blo;

    auto load_stage = [&](int it) {
        const int k0 = it * 32;
        const uint32_t sbase = sb + (uint32_t)(it % 3) * GSTG;
#pragma unroll
        for (int t = 0; t < 2; t++) {
            int idx = tid + t * 256;
            int row = idx >> 2;
            int c16 = idx & 3;
            uint32_t sw = (uint32_t)(row * 64 + ((c16 ^ ((row >> 1) & 3)) * 16));
            size_t goA = ((size_t)(m0 + row) * Fd + k0) * 2 + c16 * 16;
            size_t goB = ((size_t)(n0 + row) * Fd + k0) * 2 + c16 * 16;
            CPA(sbase +     0 + sw, pAh + goA);
            CPA(sbase +  8192 + sw, pAl + goA);
            CPA(sbase + 16384 + sw, pBh + goB);
            CPA(sbase + 24576 + sw, pBl + goB);
        }
        CPC();
    };

    const int g = lane >> 3, r8 = lane & 7;

    auto compute = [&](uint32_t sbase) {
        const uint32_t abase = sbase;
        const uint32_t bbase = sbase + 16384;
#pragma unroll
        for (int ks = 0; ks < 2; ks++) {
            uint32_t ah[16], al[16];
            const int arow = (g & 1) * 8 + r8;
            const int ac16 = 2 * ks + (g >> 1);
#pragma unroll
            for (int mi = 0; mi < 4; mi++) {
                int r = wm + mi * 16 + arow;
                uint32_t sw = (uint32_t)(r * 64 + ((ac16 ^ ((r >> 1) & 3)) * 16));
                ldsm4(&ah[mi * 4], abase + sw);
                ldsm4(&al[mi * 4], abase + 8192 + sw);
            }
#pragma unroll
            for (int j2 = 0; j2 < 2; j2++) {
                uint32_t bh[4], bl[4];
                int br = wn + (2 * j2 + (g >> 1)) * 8 + r8;
                int bc16 = 2 * ks + (g & 1);
                uint32_t sw = (uint32_t)(br * 64 + ((bc16 ^ ((br >> 1) & 3)) * 16));
                ldsm4(bh, bbase + sw);
                ldsm4(bl, bbase + 8192 + sw);
#pragma unroll
                for (int mi = 0; mi < 4; mi++) {
                    mma16816(c[mi][2*j2],     &ah[mi * 4], bh[0], bh[1]);
                    mma16816(c[mi][2*j2 + 1], &ah[mi * 4], bh[2], bh[3]);
                }
#pragma unroll
                for (int mi = 0; mi < 4; mi++) {
                    mma16816(c[mi][2*j2],     &ah[mi * 4], bl[0], bl[1]);
                    mma16816(c[mi][2*j2 + 1], &ah[mi * 4], bl[2], bl[3]);
                }
#pragma unroll
                for (int mi = 0; mi < 4; mi++) {
                    mma16816(c[mi][2*j2],     &al[mi * 4], bh[0], bh[1]);
                    mma16816(c[mi][2*j2 + 1], &al[mi * 4], bh[2], bh[3]);
                }
            }
        }
    };

    load_stage(0);
    load_stage(1);
    for (int it = 0; it < Fd / 32; it++) {
        CPW1();
        __syncthreads();
        if (it + 2 < Fd / 32) load_stage(it + 2);
        compute(sb + (uint32_t)(it % 3) * GSTG);
    }

    const int crow = lane >> 2;
    const int ccol = (lane & 3) * 2;
#pragma unroll
    for (int mi = 0; mi < 4; mi++) {
#pragma unroll
        for (int nj = 0; nj < 4; nj++) {
            const int m = m0 + wm + mi * 16 + crow;
            const int n = n0 + wn + nj * 8 + ccol;
            const float b0 = __ldg(&bias[n]);
            const float b1 = __ldg(&bias[n + 1]);
            float v00 = (c[mi][nj][0] + b0) * scale;
            float v01 = (c[mi][nj][1] + b1) * scale;
            float v10 = (c[mi][nj][2] + b0) * scale;
            float v11 = (c[mi][nj][3] + b1) * scale;
            if (MODE == 0) {
                float2 o0 = {v00, v01}, o1 = {v10, v11};
                *reinterpret_cast<float2*>(&C[(size_t)m * Fd + n]) = o0;
                *reinterpret_cast<float2*>(&C[(size_t)(m + 8) * Fd + n]) = o1;
            } else {
                const int bb = m >> 10, ss = m & 1023;
                const int hh = n >> 6, dd = n & 63;
                size_t off0 = (((size_t)(bb * Hh + hh)) * Sq + ss) * Dd + dd;
                size_t off1 = off0 + 8 * Dd;
                __nv_bfloat16 h00 = __float2bfloat16(v00);
                __nv_bfloat16 h01 = __float2bfloat16(v01);
                __nv_bfloat16 h10 = __float2bfloat16(v10);
                __nv_bfloat16 h11 = __float2bfloat16(v11);
                __nv_bfloat162 hp0 = __nv_bfloat162(h00, h01);
                __nv_bfloat162 hp1 = __nv_bfloat162(h10, h11);
                *reinterpret_cast<uint32_t*>(&Chi[off0]) = *reinterpret_cast<uint32_t*>(&hp0);
                *reinterpret_cast<uint32_t*>(&Chi[off1]) = *reinterpret_cast<uint32_t*>(&hp1);
                if (MODE == 1) {
                    __nv_bfloat162 lp0 = __nv_bfloat162(
                        __float2bfloat16(v00 - __bfloat162float(h00)),
                        __float2bfloat16(v01 - __bfloat162float(h01)));
                    __nv_bfloat162 lp1 = __nv_bfloat162(
                        __float2bfloat16(v10 - __bfloat162float(h10)),
                        __float2bfloat16(v11 - __bfloat162float(h11)));
                    *reinterpret_cast<uint32_t*>(&Clo[off0]) = *reinterpret_cast<uint32_t*>(&lp0);
                    *reinterpret_cast<uint32_t*>(&Clo[off1]) = *reinterpret_cast<uint32_t*>(&lp1);
                }
            }
        }
    }
}

__global__ __launch_bounds__(256, 2) void qkv_gemm(
    const float* __restrict__ bq, const float* __restrict__ bk,
    const float* __restrict__ bv)
{
    const int z = blockIdx.z;
    const int m0 = blockIdx.y * 128, n0 = blockIdx.x * 128;
    if (z == 0) {
        gemm_mma<1>(g_xhi, g_xlo, g_wthi, g_wtlo, bq, 0.125f,
                    nullptr, g_qh, g_ql, m0, n0);
    } else if (z == 1) {
        gemm_mma<2>(g_xhi, g_xlo, g_wthi + (size_t)Fd * Fd, g_wtlo + (size_t)Fd * Fd,
                    bk, 1.0f, nullptr, g_kh, nullptr, m0, n0);
    } else {
        gemm_mma<1>(g_xhi, g_xlo, g_wthi + (size_t)2 * Fd * Fd, g_wtlo + (size_t)2 * Fd * Fd,
                    bv, 1.0f, nullptr, g_vh, g_vl, m0, n0);
    }
}

__global__ __launch_bounds__(256, 2) void out_gemm(
    const float* __restrict__ bo, float* __restrict__ out)
{
    gemm_mma<0>(g_yhi, g_ylo,
                g_wthi + (size_t)3 * Fd * Fd, g_wtlo + (size_t)3 * Fd * Fd,
                bo, 1.0f, out, nullptr, nullptr,
                blockIdx.y * 128, blockIdx.x * 128);
}

// ---------------------------------------------------------------------------
// Flash attention: no-max softmax, R via __ldg, K single bf16 (2-term QK),
// V hi/lo (3-term PV). 64 q-rows/CTA, 32-key tiles, 2-stage ring with the
// proven R10 wait-after-compute ordering. Dedicated Q staging region.
// smem: 2 stages x 13824 + Q 18432 = 46080; 4 CTAs/SM = 184KB.
// ---------------------------------------------------------------------------
#define AKH 0
#define AVH 4608
#define AVL 9216
#define ASTG 13824
#define AQH  (2*ASTG)
#define AQL  (AQH + 9216)
#define ASMEM (AQL + 9216)
#define KVPITCH 144
#define NKT 32

__global__ __launch_bounds__(128, 4) void attn_mma(const float* __restrict__ R)
{
    extern __shared__ __align__(128) char smem[];
    const uint32_t sb = smem_u32(smem);
    const int tid = threadIdx.x;
    const int lane = tid & 31, w = tid >> 5;
    const int bb = blockIdx.x;
    const int hh = blockIdx.y >> 4;
    const int qt = blockIdx.y & 15;
    const int bh = bb * Hh + hh;

    const int lr = lane & 7;
    const int sel8  = (lane & 8) ? 8 : 0;
    const int sel16 = (lane & 16) ? 8 : 0;
    const int crow = lane >> 2;
    const int ct = (lane & 3) * 2;

    const __nv_bfloat16* Kh = g_kh + (size_t)bh * Sq * Dd;
    const __nv_bfloat16* Vh = g_vh + (size_t)bh * Sq * Dd;
    const __nv_bfloat16* Vl = g_vl + (size_t)bh * Sq * Dd;
    const int rrow0 = w * 16 + crow;
    const float* Rrow0 = R + (size_t)hh * Sq * Sq + (size_t)(qt * 64 + rrow0) * Sq;
    const float* Rrow1 = Rrow0 + 8 * (size_t)Sq;

    auto load_stage = [&](int stg, int kt) {
        const int k0 = kt * 32;
        const uint32_t sbase = sb + stg * ASTG;
#pragma unroll
        for (int i = 0; i < 2; i++) {
            int idx = tid + i * 128;
            int row = idx >> 3;
            int seg = (idx & 7) * 16;
            uint32_t so = sbase + row * KVPITCH + seg;
            size_t go = ((size_t)(k0 + row)) * Dd + (seg >> 1);
            CPA(so + AKH, Kh + go);
            CPA(so + AVH, Vh + go);
            CPA(so + AVL, Vl + go);
        }
        CPC();
    };

    // ---- stage-0 prefetch + Q staging into dedicated region ----
    load_stage(0, 0);
    {
        const __nv_bfloat16* Qh = g_qh + ((size_t)bh * Sq + qt * 64) * Dd;
        const __nv_bfloat16* Ql = g_ql + ((size_t)bh * Sq + qt * 64) * Dd;
#pragma unroll
        for (int i = 0; i < 4; i++) {
            int idx = tid + i * 128;
            int row = idx >> 3;
            int seg = (idx & 7) * 16;
            uint32_t so = sb + AQH + row * KVPITCH + seg;
            size_t go = (size_t)row * Dd + (seg >> 1);
            CPA(so, Qh + go);
            CPA(so + 9216, Ql + go);
        }
        CPC();
    }
    CPW0();
    __syncthreads();

    uint32_t qfh[4][4], qfl[4][4];
    {
        const int arow = w * 16 + lr + sel8;
#pragma unroll
        for (int cc = 0; cc < 4; cc++) {
            const int acol = cc * 16 + sel16;
            uint32_t ad = sb + AQH + (uint32_t)(arow * KVPITCH + acol * 2);
            ldsm4(qfh[cc], ad);
            ldsm4(qfl[cc], ad + 9216);
        }
    }

    float o[8][4];
#pragma unroll
    for (int j = 0; j < 8; j++)
#pragma unroll
        for (int r = 0; r < 4; r++) o[j][r] = 0.0f;
    float lval0 = 0.0f, lval1 = 0.0f;

    for (int kt = 0; kt < NKT; kt++) {
        if (kt + 1 < NKT) load_stage((kt + 1) & 1, kt + 1);
        const uint32_t stg = sb + (kt & 1) * ASTG;
        const int k0 = kt * 32;

        // ---- prefetch R via LDG (hidden under QK MMAs) ----
        float2 rv0[4], rv1[4];
#pragma unroll
        for (int j = 0; j < 4; j++) {
            const int cj = k0 + j * 8 + ct;
            rv0[j] = __ldg(reinterpret_cast<const float2*>(Rrow0 + cj));
            rv1[j] = __ldg(reinterpret_cast<const float2*>(Rrow1 + cj));
        }

        // ---- QK^T (2 terms: qh*k + ql*k; K single bf16) ----
        float c[4][4];
#pragma unroll
        for (int j = 0; j < 4; j++)
#pragma unroll
            for (int r = 0; r < 4; r++) c[j][r] = 0.0f;

#pragma unroll
        for (int cc = 0; cc < 4; cc++) {
            const int bcol = cc * 16 + sel8;
            uint32_t kh0[4], kh1[4];
            {
                uint32_t kd0 = stg + (uint32_t)((lr + sel16) * KVPITCH + bcol * 2);
                uint32_t kd1 = stg + (uint32_t)((16 + lr + sel16) * KVPITCH + bcol * 2);
                ldsm4(kh0, kd0 + AKH);
                ldsm4(kh1, kd1 + AKH);
            }
            mma16816(c[0], qfh[cc], kh0[0], kh0[1]);
            mma16816(c[1], qfh[cc], kh0[2], kh0[3]);
            mma16816(c[2], qfh[cc], kh1[0], kh1[1]);
            mma16816(c[3], qfh[cc], kh1[2], kh1[3]);
            mma16816(c[0], qfl[cc], kh0[0], kh0[1]);
            mma16816(c[1], qfl[cc], kh0[2], kh0[3]);
            mma16816(c[2], qfl[cc], kh1[0], kh1[1]);
            mma16816(c[3], qfl[cc], kh1[2], kh1[3]);
        }

        // ---- add R, exp (no max shift — scores bounded), split P ----
        uint32_t pah[2][4], pal[2][4];
#pragma unroll
        for (int j = 0; j < 4; j++) {
            float p00 = __expf(c[j][0] + rv0[j].x);
            float p01 = __expf(c[j][1] + rv0[j].y);
            float p10 = __expf(c[j][2] + rv1[j].x);
            float p11 = __expf(c[j][3] + rv1[j].y);
            lval0 += p00 + p01;
            lval1 += p10 + p11;
            __nv_bfloat16 h00 = __float2bfloat16(p00);
            __nv_bfloat16 h01 = __float2bfloat16(p01);
            __nv_bfloat16 h10 = __float2bfloat16(p10);
            __nv_bfloat16 h11 = __float2bfloat16(p11);
            const int kc = j >> 1, sl = (j & 1) * 2;
            {
                __nv_bfloat162 t0 = __nv_bfloat162(h00, h01);
                __nv_bfloat162 t1 = __nv_bfloat162(h10, h11);
                pah[kc][sl]   = *reinterpret_cast<uint32_t*>(&t0);
                pah[kc][sl+1] = *reinterpret_cast<uint32_t*>(&t1);
            }
            {
                __nv_bfloat162 t0 = __nv_bfloat162(
                    __float2bfloat16(p00 - __bfloat162float(h00)),
                    __float2bfloat16(p01 - __bfloat162float(h01)));
                __nv_bfloat162 t1 = __nv_bfloat162(
                    __float2bfloat16(p10 - __bfloat162float(h10)),
                    __float2bfloat16(p11 - __bfloat162float(h11)));
                pal[kc][sl]   = *reinterpret_cast<uint32_t*>(&t0);
                pal[kc][sl+1] = *reinterpret_cast<uint32_t*>(&t1);
            }
        }

        // ---- P @ V (3 terms: ph*vh + ph*vl + pl*vh) ----
#pragma unroll
        for (int kc = 0; kc < 2; kc++) {
            const int vrow = kc * 16 + lr + sel8;
#pragma unroll
            for (int npp = 0; npp < 4; npp += 2) {
                uint32_t vhA[4], vlA[4], vhB[4], vlB[4];
                uint32_t vdA = stg + (uint32_t)(vrow * KVPITCH + (npp * 16 + sel16) * 2);
                uint32_t vdB = stg + (uint32_t)(vrow * KVPITCH + ((npp + 1) * 16 + sel16) * 2);
                ldsm4t(vhA, vdA + AVH);
                ldsm4t(vlA, vdA + AVL);
                ldsm4t(vhB, vdB + AVH);
                ldsm4t(vlB, vdB + AVL);
                mma16816(o[2*npp],     pah[kc], vhA[0], vhA[1]);
                mma16816(o[2*npp + 1], pah[kc], vhA[2], vhA[3]);
                mma16816(o[2*npp + 2], pah[kc], vhB[0], vhB[1]);
                mma16816(o[2*npp + 3], pah[kc], vhB[2], vhB[3]);
                mma16816(o[2*npp],     pah[kc], vlA[0], vlA[1]);
                mma16816(o[2*npp + 1], pah[kc], vlA[2], vlA[3]);
                mma16816(o[2*npp + 2], pah[kc], vlB[0], vlB[1]);
                mma16816(o[2*npp + 3], pah[kc], vlB[2], vlB[3]);
                mma16816(o[2*npp],     pal[kc], vhA[0], vhA[1]);
                mma16816(o[2*npp + 1], pal[kc], vhA[2], vhA[3]);
                mma16816(o[2*npp + 2], pal[kc], vhB[0], vhB[1]);
                mma16816(o[2*npp + 3], pal[kc], vhB[2], vhB[3]);
            }
        }

        CPW0();
        __syncthreads();
    }

    // ---- single cross-lane reduction of l, normalize, write ----
    lval0 += __shfl_xor_sync(0xffffffffu, lval0, 1);
    lval0 += __shfl_xor_sync(0xffffffffu, lval0, 2);
    lval1 += __shfl_xor_sync(0xffffffffu, lval1, 1);
    lval1 += __shfl_xor_sync(0xffffffffu, lval1, 2);
    const float inv0 = 1.0f / lval0;
    const float inv1 = 1.0f / lval1;
    const int row0 = bb * Sq + qt * 64 + w * 16 + crow;
#pragma unroll
    for (int j = 0; j < 8; j++) {
        const int col = hh * Dd + j * 8 + ct;
        float v00 = o[j][0] * inv0, v01 = o[j][1] * inv0;
        float v10 = o[j][2] * inv1, v11 = o[j][3] * inv1;
        __nv_bfloat16 h00 = __float2bfloat16(v00);
        __nv_bfloat16 h01 = __float2bfloat16(v01);
        __nv_bfloat16 h10 = __float2bfloat16(v10);
        __nv_bfloat16 h11 = __float2bfloat16(v11);
        __nv_bfloat162 hp0 = __nv_bfloat162(h00, h01);
        __nv_bfloat162 hp1 = __nv_bfloat162(h10, h11);
        __nv_bfloat162 lp0 = __nv_bfloat162(
            __float2bfloat16(v00 - __bfloat162float(h00)),
            __float2bfloat16(v01 - __bfloat162float(h01)));
        __nv_bfloat162 lp1 = __nv_bfloat162(
            __float2bfloat16(v10 - __bfloat162float(h10)),
            __float2bfloat16(v11 - __bfloat162float(h11)));
        size_t off0 = (size_t)row0 * Fd + col;
        size_t off1 = off0 + 8 * (size_t)Fd;
        *reinterpret_cast<uint32_t*>(&g_yhi[off0]) = *reinterpret_cast<uint32_t*>(&hp0);
        *reinterpret_cast<uint32_t*>(&g_yhi[off1]) = *reinterpret_cast<uint32_t*>(&hp1);
        *reinterpret_cast<uint32_t*>(&g_ylo[off0]) = *reinterpret_cast<uint32_t*>(&lp0);
        *reinterpret_cast<uint32_t*>(&g_ylo[off1]) = *reinterpret_cast<uint32_t*>(&lp1);
    }
}

// ---------------------------------------------------------------------------
extern "C" void kernel_launch(void* const* d_in, const int* in_sizes, int n_in,
                              void* d_out, int out_size)
{
    const float* inputs_q = (const float*)d_in[0];
    const float* Wq = (const float*)d_in[1];
    const float* bq = (const float*)d_in[2];
    const float* Wk = (const float*)d_in[3];
    const float* bk = (const float*)d_in[4];
    const float* Wv = (const float*)d_in[5];
    const float* bv = (const float*)d_in[6];
    const float* R  = (const float*)d_in[7];
    const float* Wo = (const float*)d_in[8];
    const float* bo = (const float*)d_in[9];
    float* out = (float*)d_out;

    cudaFuncSetAttribute(qkv_gemm, cudaFuncAttributeMaxDynamicSharedMemorySize, GSMEM);
    cudaFuncSetAttribute(out_gemm, cudaFuncAttributeMaxDynamicSharedMemorySize, GSMEM);
    cudaFuncSetAttribute(attn_mma, cudaFuncAttributeMaxDynamicSharedMemorySize, ASMEM);

    split_x<<<4096, 256>>>(inputs_q);
    split_wt<<<dim3(32, 32, 4), dim3(32, 8)>>>(Wq, Wk, Wv, Wo);

    qkv_gemm<<<dim3(Fd / 128, (Bsz * Sq) / 128, 3), 256, GSMEM>>>(bq, bk, bv);

    attn_mma<<<dim3(Bsz, Hh * 16), 128, ASMEM>>>(R);

    out_gemm<<<dim3(Fd / 128, (Bsz * Sq) / 128), 256, GSMEM>>>(bo, out);
}

// round 15
// speedup vs baseline: 1.8033x; 1.0936x over previous
#include <cuda_runtime.h>
#include <cuda_bf16.h>
#include <math.h>
#include <stdint.h>

#define Bsz 4
#define Sq  1024
#define Fd  1024
#define Hh  16
#define Dd  64

// ---------------------------------------------------------------------------
// Scratch (device globals)
// ---------------------------------------------------------------------------
__device__ __nv_bfloat16 g_xhi[Bsz*Sq*Fd];
__device__ __nv_bfloat16 g_xlo[Bsz*Sq*Fd];
__device__ __nv_bfloat16 g_wthi[4*Fd*Fd];   // [N][K] x4 (Wq,Wk,Wv,Wo)
__device__ __nv_bfloat16 g_wtlo[4*Fd*Fd];
__device__ __nv_bfloat16 g_qh[Bsz*Hh*Sq*Dd];
__device__ __nv_bfloat16 g_ql[Bsz*Hh*Sq*Dd];
__device__ __nv_bfloat16 g_kh[Bsz*Hh*Sq*Dd];   // K single bf16 (softmax damps K error)
__device__ __nv_bfloat16 g_vh[Bsz*Hh*Sq*Dd];
__device__ __nv_bfloat16 g_vl[Bsz*Hh*Sq*Dd];
__device__ __nv_bfloat16 g_yhi[Bsz*Sq*Fd];
__device__ __nv_bfloat16 g_ylo[Bsz*Sq*Fd];

// ---------------------------------------------------------------------------
// PTX helpers (baseline PTX only)
// ---------------------------------------------------------------------------
__device__ __forceinline__ uint32_t smem_u32(const void* p) {
    uint32_t a;
    asm("{ .reg .u64 t; cvta.to.shared.u64 t, %1; cvt.u32.u64 %0, t; }"
        : "=r"(a) : "l"(p));
    return a;
}

// .cg: bypass L1 allocation (global data is smem-bound, never re-read via L1)
#define CPA(dst, src) do {                                                   \
    uint64_t _g = __cvta_generic_to_global((const void*)(src));              \
    asm volatile("cp.async.cg.shared.global [%0], [%1], 16;"                 \
                 :: "r"(dst), "l"(_g) : "memory");                           \
} while (0)
#define CPC() asm volatile("cp.async.commit_group;" ::: "memory")
#define CPW0() asm volatile("cp.async.wait_group 0;" ::: "memory")
#define CPW1() asm volatile("cp.async.wait_group 1;" ::: "memory")

__device__ __forceinline__ void ldsm4(uint32_t r[4], uint32_t addr) {
    asm volatile("ldmatrix.sync.aligned.m8n8.x4.shared.b16 {%0,%1,%2,%3}, [%4];"
        : "=r"(r[0]), "=r"(r[1]), "=r"(r[2]), "=r"(r[3]) : "r"(addr));
}
__device__ __forceinline__ void ldsm4t(uint32_t r[4], uint32_t addr) {
    asm volatile("ldmatrix.sync.aligned.m8n8.x4.trans.shared.b16 {%0,%1,%2,%3}, [%4];"
        : "=r"(r[0]), "=r"(r[1]), "=r"(r[2]), "=r"(r[3]) : "r"(addr));
}

__device__ __forceinline__ void mma16816(float* c, const uint32_t* a,
                                         uint32_t b0, uint32_t b1) {
    asm volatile("mma.sync.aligned.m16n8k16.row.col.f32.bf16.bf16.f32 "
        "{%0,%1,%2,%3}, {%4,%5,%6,%7}, {%8,%9}, {%0,%1,%2,%3};"
        : "+f"(c[0]), "+f"(c[1]), "+f"(c[2]), "+f"(c[3])
        : "r"(a[0]), "r"(a[1]), "r"(a[2]), "r"(a[3]), "r"(b0), "r"(b1));
}

// ---------------------------------------------------------------------------
// Conversions
// ---------------------------------------------------------------------------
__global__ void split_x(const float* __restrict__ X) {
    int i = (blockIdx.x * blockDim.x + threadIdx.x) * 4;
    float4 v = *reinterpret_cast<const float4*>(&X[i]);
    float vv[4] = {v.x, v.y, v.z, v.w};
#pragma unroll
    for (int j = 0; j < 4; j++) {
        __nv_bfloat16 h = __float2bfloat16(vv[j]);
        g_xhi[i + j] = h;
        g_xlo[i + j] = __float2bfloat16(vv[j] - __bfloat162float(h));
    }
}

__global__ void split_wt(const float* __restrict__ Wq, const float* __restrict__ Wk,
                         const float* __restrict__ Wv, const float* __restrict__ Wo) {
    __shared__ float t[32][33];
    const int z = blockIdx.z;
    const float* __restrict__ W = (z == 0) ? Wq : (z == 1) ? Wk : (z == 2) ? Wv : Wo;
    __nv_bfloat16* hi = g_wthi + (size_t)z * Fd * Fd;
    __nv_bfloat16* lo = g_wtlo + (size_t)z * Fd * Fd;

    const int tx = threadIdx.x, ty = threadIdx.y;
    const int kbase = blockIdx.y * 32, nbase = blockIdx.x * 32;
#pragma unroll
    for (int i = 0; i < 4; i++) {
        int kr = ty * 4 + i;
        t[kr][tx] = W[(size_t)(kbase + kr) * Fd + nbase + tx];
    }
    __syncthreads();
#pragma unroll
    for (int i = 0; i < 4; i++) {
        int nr = ty * 4 + i;
        float v = t[tx][nr];
        __nv_bfloat16 h = __float2bfloat16(v);
        size_t o = (size_t)(nbase + nr) * Fd + kbase + tx;
        hi[o] = h;
        lo[o] = __float2bfloat16(v - __bfloat162float(h));
    }
}

// ---------------------------------------------------------------------------
// mma.sync GEMM: bf16 3-term hi/lo, 3-stage cp.async ring, XOR-swizzled smem.
// BM=128, BN=128, BK=32, 8 warps (2m x 4n), warp tile 64x32. (R8 config)
// MODE: 0 = fp32 C + bias. 1 = hi/lo bf16 [B,H,S,D]. 2 = hi-only bf16 [B,H,S,D].
// ---------------------------------------------------------------------------
#define GSTG  32768
#define GSMEM (3*GSTG)

template<int MODE>
__device__ __forceinline__ void gemm_mma(
    const __nv_bfloat16* __restrict__ Ahi, const __nv_bfloat16* __restrict__ Alo,
    const __nv_bfloat16* __restrict__ Bhi, const __nv_bfloat16* __restrict__ Blo,
    const float* __restrict__ bias, float scale,
    float* __restrict__ C, __nv_bfloat16* __restrict__ Chi,
    __nv_bfloat16* __restrict__ Clo,
    int m0, int n0)
{
    extern __shared__ __align__(128) char smem[];
    const uint32_t sb = smem_u32(smem);
    const int tid = threadIdx.x;
    const int lane = tid & 31, wid = tid >> 5;
    const int wm = (wid >> 2) * 64;
    const int wn = (wid & 3) * 32;

    float c[4][4][4];
#pragma unroll
    for (int i = 0; i < 4; i++)
#pragma unroll
        for (int j = 0; j < 4; j++)
#pragma unroll
            for (int r = 0; r < 4; r++) c[i][j][r] = 0.0f;

    const char* pAh = (const char*)Ahi;
    const char* pAl = (const char*)Alo;
    const char* pBh = (const char*)Bhi;
    const char* pBl = (const char*)Blo;

    auto load_stage = [&](int it) {
        const int k0 = it * 32;
        const uint32_t sbase = sb + (uint32_t)(it % 3) * GSTG;
#pragma unroll
        for (int t = 0; t < 2; t++) {
            int idx = tid + t * 256;
            int row = idx >> 2;
            int c16 = idx & 3;
            uint32_t sw = (uint32_t)(row * 64 + ((c16 ^ ((row >> 1) & 3)) * 16));
            size_t goA = ((size_t)(m0 + row) * Fd + k0) * 2 + c16 * 16;
            size_t goB = ((size_t)(n0 + row) * Fd + k0) * 2 + c16 * 16;
            CPA(sbase +     0 + sw, pAh + goA);
            CPA(sbase +  8192 + sw, pAl + goA);
            CPA(sbase + 16384 + sw, pBh + goB);
            CPA(sbase + 24576 + sw, pBl + goB);
        }
        CPC();
    };

    const int g = lane >> 3, r8 = lane & 7;

    auto compute = [&](uint32_t sbase) {
        const uint32_t abase = sbase;
        const uint32_t bbase = sbase + 16384;
#pragma unroll
        for (int ks = 0; ks < 2; ks++) {
            uint32_t ah[16], al[16];
            const int arow = (g & 1) * 8 + r8;
            const int ac16 = 2 * ks + (g >> 1);
#pragma unroll
            for (int mi = 0; mi < 4; mi++) {
                int r = wm + mi * 16 + arow;
                uint32_t sw = (uint32_t)(r * 64 + ((ac16 ^ ((r >> 1) & 3)) * 16));
                ldsm4(&ah[mi * 4], abase + sw);
                ldsm4(&al[mi * 4], abase + 8192 + sw);
            }
#pragma unroll
            for (int j2 = 0; j2 < 2; j2++) {
                uint32_t bh[4], bl[4];
                int br = wn + (2 * j2 + (g >> 1)) * 8 + r8;
                int bc16 = 2 * ks + (g & 1);
                uint32_t sw = (uint32_t)(br * 64 + ((bc16 ^ ((br >> 1) & 3)) * 16));
                ldsm4(bh, bbase + sw);
                ldsm4(bl, bbase + 8192 + sw);
#pragma unroll
                for (int mi = 0; mi < 4; mi++) {
                    mma16816(c[mi][2*j2],     &ah[mi * 4], bh[0], bh[1]);
                    mma16816(c[mi][2*j2 + 1], &ah[mi * 4], bh[2], bh[3]);
                }
#pragma unroll
                for (int mi = 0; mi < 4; mi++) {
                    mma16816(c[mi][2*j2],     &ah[mi * 4], bl[0], bl[1]);
                    mma16816(c[mi][2*j2 + 1], &ah[mi * 4], bl[2], bl[3]);
                }
#pragma unroll
                for (int mi = 0; mi < 4; mi++) {
                    mma16816(c[mi][2*j2],     &al[mi * 4], bh[0], bh[1]);
                    mma16816(c[mi][2*j2 + 1], &al[mi * 4], bh[2], bh[3]);
                }
            }
        }
    };

    load_stage(0);
    load_stage(1);
    for (int it = 0; it < Fd / 32; it++) {
        CPW1();
        __syncthreads();
        if (it + 2 < Fd / 32) load_stage(it + 2);
        compute(sb + (uint32_t)(it % 3) * GSTG);
    }

    const int crow = lane >> 2;
    const int ccol = (lane & 3) * 2;
#pragma unroll
    for (int mi = 0; mi < 4; mi++) {
#pragma unroll
        for (int nj = 0; nj < 4; nj++) {
            const int m = m0 + wm + mi * 16 + crow;
            const int n = n0 + wn + nj * 8 + ccol;
            const float b0 = __ldg(&bias[n]);
            const float b1 = __ldg(&bias[n + 1]);
            float v00 = (c[mi][nj][0] + b0) * scale;
            float v01 = (c[mi][nj][1] + b1) * scale;
            float v10 = (c[mi][nj][2] + b0) * scale;
            float v11 = (c[mi][nj][3] + b1) * scale;
            if (MODE == 0) {
                float2 o0 = {v00, v01}, o1 = {v10, v11};
                *reinterpret_cast<float2*>(&C[(size_t)m * Fd + n]) = o0;
                *reinterpret_cast<float2*>(&C[(size_t)(m + 8) * Fd + n]) = o1;
            } else {
                const int bb = m >> 10, ss = m & 1023;
                const int hh = n >> 6, dd = n & 63;
                size_t off0 = (((size_t)(bb * Hh + hh)) * Sq + ss) * Dd + dd;
                size_t off1 = off0 + 8 * Dd;
                __nv_bfloat16 h00 = __float2bfloat16(v00);
                __nv_bfloat16 h01 = __float2bfloat16(v01);
                __nv_bfloat16 h10 = __float2bfloat16(v10);
                __nv_bfloat16 h11 = __float2bfloat16(v11);
                __nv_bfloat162 hp0 = __nv_bfloat162(h00, h01);
                __nv_bfloat162 hp1 = __nv_bfloat162(h10, h11);
                *reinterpret_cast<uint32_t*>(&Chi[off0]) = *reinterpret_cast<uint32_t*>(&hp0);
                *reinterpret_cast<uint32_t*>(&Chi[off1]) = *reinterpret_cast<uint32_t*>(&hp1);
                if (MODE == 1) {
                    __nv_bfloat162 lp0 = __nv_bfloat162(
                        __float2bfloat16(v00 - __bfloat162float(h00)),
                        __float2bfloat16(v01 - __bfloat162float(h01)));
                    __nv_bfloat162 lp1 = __nv_bfloat162(
                        __float2bfloat16(v10 - __bfloat162float(h10)),
                        __float2bfloat16(v11 - __bfloat162float(h11)));
                    *reinterpret_cast<uint32_t*>(&Clo[off0]) = *reinterpret_cast<uint32_t*>(&lp0);
                    *reinterpret_cast<uint32_t*>(&Clo[off1]) = *reinterpret_cast<uint32_t*>(&lp1);
                }
            }
        }
    }
}

__global__ __launch_bounds__(256, 2) void qkv_gemm(
    const float* __restrict__ bq, const float* __restrict__ bk,
    const float* __restrict__ bv)
{
    const int z = blockIdx.z;
    const int m0 = blockIdx.y * 128, n0 = blockIdx.x * 128;
    if (z == 0) {
        gemm_mma<1>(g_xhi, g_xlo, g_wthi, g_wtlo, bq, 0.125f,
                    nullptr, g_qh, g_ql, m0, n0);
    } else if (z == 1) {
        gemm_mma<2>(g_xhi, g_xlo, g_wthi + (size_t)Fd * Fd, g_wtlo + (size_t)Fd * Fd,
                    bk, 1.0f, nullptr, g_kh, nullptr, m0, n0);
    } else {
        gemm_mma<1>(g_xhi, g_xlo, g_wthi + (size_t)2 * Fd * Fd, g_wtlo + (size_t)2 * Fd * Fd,
                    bv, 1.0f, nullptr, g_vh, g_vl, m0, n0);
    }
}

__global__ __launch_bounds__(256, 2) void out_gemm(
    const float* __restrict__ bo, float* __restrict__ out)
{
    gemm_mma<0>(g_yhi, g_ylo,
                g_wthi + (size_t)3 * Fd * Fd, g_wtlo + (size_t)3 * Fd * Fd,
                bo, 1.0f, out, nullptr, nullptr,
                blockIdx.y * 128, blockIdx.x * 128);
}

// ---------------------------------------------------------------------------
// Flash attention: no-max softmax, R via __ldg, K single bf16 (2-term QK),
// V hi/lo (3-term PV). 64 q-rows/CTA, 32-key tiles, 2-stage ring,
// wait-after-compute ordering. Dedicated Q staging region. 4 CTAs/SM.
// ---------------------------------------------------------------------------
#define AKH 0
#define AVH 4608
#define AVL 9216
#define ASTG 13824
#define AQH  (2*ASTG)
#define AQL  (AQH + 9216)
#define ASMEM (AQL + 9216)
#define KVPITCH 144
#define NKT 32

__global__ __launch_bounds__(128, 4) void attn_mma(const float* __restrict__ R)
{
    extern __shared__ __align__(128) char smem[];
    const uint32_t sb = smem_u32(smem);
    const int tid = threadIdx.x;
    const int lane = tid & 31, w = tid >> 5;
    const int bb = blockIdx.x;
    const int hh = blockIdx.y >> 4;
    const int qt = blockIdx.y & 15;
    const int bh = bb * Hh + hh;

    const int lr = lane & 7;
    const int sel8  = (lane & 8) ? 8 : 0;
    const int sel16 = (lane & 16) ? 8 : 0;
    const int crow = lane >> 2;
    const int ct = (lane & 3) * 2;

    const __nv_bfloat16* Kh = g_kh + (size_t)bh * Sq * Dd;
    const __nv_bfloat16* Vh = g_vh + (size_t)bh * Sq * Dd;
    const __nv_bfloat16* Vl = g_vl + (size_t)bh * Sq * Dd;
    const int rrow0 = w * 16 + crow;
    const float* Rrow0 = R + (size_t)hh * Sq * Sq + (size_t)(qt * 64 + rrow0) * Sq;
    const float* Rrow1 = Rrow0 + 8 * (size_t)Sq;

    auto load_stage = [&](int stg, int kt) {
        const int k0 = kt * 32;
        const uint32_t sbase = sb + stg * ASTG;
#pragma unroll
        for (int i = 0; i < 2; i++) {
            int idx = tid + i * 128;
            int row = idx >> 3;
            int seg = (idx & 7) * 16;
            uint32_t so = sbase + row * KVPITCH + seg;
            size_t go = ((size_t)(k0 + row)) * Dd + (seg >> 1);
            CPA(so + AKH, Kh + go);
            CPA(so + AVH, Vh + go);
            CPA(so + AVL, Vl + go);
        }
        CPC();
    };

    // ---- stage-0 prefetch + Q staging into dedicated region ----
    load_stage(0, 0);
    {
        const __nv_bfloat16* Qh = g_qh + ((size_t)bh * Sq + qt * 64) * Dd;
        const __nv_bfloat16* Ql = g_ql + ((size_t)bh * Sq + qt * 64) * Dd;
#pragma unroll
        for (int i = 0; i < 4; i++) {
            int idx = tid + i * 128;
            int row = idx >> 3;
            int seg = (idx & 7) * 16;
            uint32_t so = sb + AQH + row * KVPITCH + seg;
            size_t go = (size_t)row * Dd + (seg >> 1);
            CPA(so, Qh + go);
            CPA(so + 9216, Ql + go);
        }
        CPC();
    }
    CPW0();
    __syncthreads();

    uint32_t qfh[4][4], qfl[4][4];
    {
        const int arow = w * 16 + lr + sel8;
#pragma unroll
        for (int cc = 0; cc < 4; cc++) {
            const int acol = cc * 16 + sel16;
            uint32_t ad = sb + AQH + (uint32_t)(arow * KVPITCH + acol * 2);
            ldsm4(qfh[cc], ad);
            ldsm4(qfl[cc], ad + 9216);
        }
    }

    float o[8][4];
#pragma unroll
    for (int j = 0; j < 8; j++)
#pragma unroll
        for (int r = 0; r < 4; r++) o[j][r] = 0.0f;
    float lval0 = 0.0f, lval1 = 0.0f;

    for (int kt = 0; kt < NKT; kt++) {
        if (kt + 1 < NKT) load_stage((kt + 1) & 1, kt + 1);
        const uint32_t stg = sb + (kt & 1) * ASTG;
        const int k0 = kt * 32;

        // ---- prefetch R via LDG (hidden under QK MMAs) ----
        float2 rv0[4], rv1[4];
#pragma unroll
        for (int j = 0; j < 4; j++) {
            const int cj = k0 + j * 8 + ct;
            rv0[j] = __ldg(reinterpret_cast<const float2*>(Rrow0 + cj));
            rv1[j] = __ldg(reinterpret_cast<const float2*>(Rrow1 + cj));
        }

        // ---- QK^T (2 terms: qh*k + ql*k; K single bf16) ----
        float c[4][4];
#pragma unroll
        for (int j = 0; j < 4; j++)
#pragma unroll
            for (int r = 0; r < 4; r++) c[j][r] = 0.0f;

#pragma unroll
        for (int cc = 0; cc < 4; cc++) {
            const int bcol = cc * 16 + sel8;
            uint32_t kh0[4], kh1[4];
            {
                uint32_t kd0 = stg + (uint32_t)((lr + sel16) * KVPITCH + bcol * 2);
                uint32_t kd1 = stg + (uint32_t)((16 + lr + sel16) * KVPITCH + bcol * 2);
                ldsm4(kh0, kd0 + AKH);
                ldsm4(kh1, kd1 + AKH);
            }
            mma16816(c[0], qfh[cc], kh0[0], kh0[1]);
            mma16816(c[1], qfh[cc], kh0[2], kh0[3]);
            mma16816(c[2], qfh[cc], kh1[0], kh1[1]);
            mma16816(c[3], qfh[cc], kh1[2], kh1[3]);
            mma16816(c[0], qfl[cc], kh0[0], kh0[1]);
            mma16816(c[1], qfl[cc], kh0[2], kh0[3]);
            mma16816(c[2], qfl[cc], kh1[0], kh1[1]);
            mma16816(c[3], qfl[cc], kh1[2], kh1[3]);
        }

        // ---- add R, exp (no max shift — scores bounded), split P ----
        uint32_t pah[2][4], pal[2][4];
#pragma unroll
        for (int j = 0; j < 4; j++) {
            float p00 = __expf(c[j][0] + rv0[j].x);
            float p01 = __expf(c[j][1] + rv0[j].y);
            float p10 = __expf(c[j][2] + rv1[j].x);
            float p11 = __expf(c[j][3] + rv1[j].y);
            lval0 += p00 + p01;
            lval1 += p10 + p11;
            __nv_bfloat16 h00 = __float2bfloat16(p00);
            __nv_bfloat16 h01 = __float2bfloat16(p01);
            __nv_bfloat16 h10 = __float2bfloat16(p10);
            __nv_bfloat16 h11 = __float2bfloat16(p11);
            const int kc = j >> 1, sl = (j & 1) * 2;
            {
                __nv_bfloat162 t0 = __nv_bfloat162(h00, h01);
                __nv_bfloat162 t1 = __nv_bfloat162(h10, h11);
                pah[kc][sl]   = *reinterpret_cast<uint32_t*>(&t0);
                pah[kc][sl+1] = *reinterpret_cast<uint32_t*>(&t1);
            }
            {
                __nv_bfloat162 t0 = __nv_bfloat162(
                    __float2bfloat16(p00 - __bfloat162float(h00)),
                    __float2bfloat16(p01 - __bfloat162float(h01)));
                __nv_bfloat162 t1 = __nv_bfloat162(
                    __float2bfloat16(p10 - __bfloat162float(h10)),
                    __float2bfloat16(p11 - __bfloat162float(h11)));
                pal[kc][sl]   = *reinterpret_cast<uint32_t*>(&t0);
                pal[kc][sl+1] = *reinterpret_cast<uint32_t*>(&t1);
            }
        }

        // ---- P @ V (3 terms: ph*vh + ph*vl + pl*vh) ----
#pragma unroll
        for (int kc = 0; kc < 2; kc++) {
            const int vrow = kc * 16 + lr + sel8;
#pragma unroll
            for (int npp = 0; npp < 4; npp += 2) {
                uint32_t vhA[4], vlA[4], vhB[4], vlB[4];
                uint32_t vdA = stg + (uint32_t)(vrow * KVPITCH + (npp * 16 + sel16) * 2);
                uint32_t vdB = stg + (uint32_t)(vrow * KVPITCH + ((npp + 1) * 16 + sel16) * 2);
                ldsm4t(vhA, vdA + AVH);
                ldsm4t(vlA, vdA + AVL);
                ldsm4t(vhB, vdB + AVH);
                ldsm4t(vlB, vdB + AVL);
                mma16816(o[2*npp],     pah[kc], vhA[0], vhA[1]);
                mma16816(o[2*npp + 1], pah[kc], vhA[2], vhA[3]);
                mma16816(o[2*npp + 2], pah[kc], vhB[0], vhB[1]);
                mma16816(o[2*npp + 3], pah[kc], vhB[2], vhB[3]);
                mma16816(o[2*npp],     pah[kc], vlA[0], vlA[1]);
                mma16816(o[2*npp + 1], pah[kc], vlA[2], vlA[3]);
                mma16816(o[2*npp + 2], pah[kc], vlB[0], vlB[1]);
                mma16816(o[2*npp + 3], pah[kc], vlB[2], vlB[3]);
                mma16816(o[2*npp],     pal[kc], vhA[0], vhA[1]);
                mma16816(o[2*npp + 1], pal[kc], vhA[2], vhA[3]);
                mma16816(o[2*npp + 2], pal[kc], vhB[0], vhB[1]);
                mma16816(o[2*npp + 3], pal[kc], vhB[2], vhB[3]);
            }
        }

        CPW0();
        __syncthreads();
    }

    // ---- single cross-lane reduction of l, normalize, write ----
    lval0 += __shfl_xor_sync(0xffffffffu, lval0, 1);
    lval0 += __shfl_xor_sync(0xffffffffu, lval0, 2);
    lval1 += __shfl_xor_sync(0xffffffffu, lval1, 1);
    lval1 += __shfl_xor_sync(0xffffffffu, lval1, 2);
    const float inv0 = 1.0f / lval0;
    const float inv1 = 1.0f / lval1;
    const int row0 = bb * Sq + qt * 64 + w * 16 + crow;
#pragma unroll
    for (int j = 0; j < 8; j++) {
        const int col = hh * Dd + j * 8 + ct;
        float v00 = o[j][0] * inv0, v01 = o[j][1] * inv0;
        float v10 = o[j][2] * inv1, v11 = o[j][3] * inv1;
        __nv_bfloat16 h00 = __float2bfloat16(v00);
        __nv_bfloat16 h01 = __float2bfloat16(v01);
        __nv_bfloat16 h10 = __float2bfloat16(v10);
        __nv_bfloat16 h11 = __float2bfloat16(v11);
        __nv_bfloat162 hp0 = __nv_bfloat162(h00, h01);
        __nv_bfloat162 hp1 = __nv_bfloat162(h10, h11);
        __nv_bfloat162 lp0 = __nv_bfloat162(
            __float2bfloat16(v00 - __bfloat162float(h00)),
            __float2bfloat16(v01 - __bfloat162float(h01)));
        __nv_bfloat162 lp1 = __nv_bfloat162(
            __float2bfloat16(v10 - __bfloat162float(h10)),
            __float2bfloat16(v11 - __bfloat162float(h11)));
        size_t off0 = (size_t)row0 * Fd + col;
        size_t off1 = off0 + 8 * (size_t)Fd;
        *reinterpret_cast<uint32_t*>(&g_yhi[off0]) = *reinterpret_cast<uint32_t*>(&hp0);
        *reinterpret_cast<uint32_t*>(&g_yhi[off1]) = *reinterpret_cast<uint32_t*>(&hp1);
        *reinterpret_cast<uint32_t*>(&g_ylo[off0]) = *reinterpret_cast<uint32_t*>(&lp0);
        *reinterpret_cast<uint32_t*>(&g_ylo[off1]) = *reinterpret_cast<uint32_t*>(&lp1);
    }
}

// ---------------------------------------------------------------------------
extern "C" void kernel_launch(void* const* d_in, const int* in_sizes, int n_in,
                              void* d_out, int out_size)
{
    const float* inputs_q = (const float*)d_in[0];
    const float* Wq = (const float*)d_in[1];
    const float* bq = (const float*)d_in[2];
    const float* Wk = (const float*)d_in[3];
    const float* bk = (const float*)d_in[4];
    const float* Wv = (const float*)d_in[5];
    const float* bv = (const float*)d_in[6];
    const float* R  = (const float*)d_in[7];
    const float* Wo = (const float*)d_in[8];
    const float* bo = (const float*)d_in[9];
    float* out = (float*)d_out;

    cudaFuncSetAttribute(qkv_gemm, cudaFuncAttributeMaxDynamicSharedMemorySize, GSMEM);
    cudaFuncSetAttribute(out_gemm, cudaFuncAttributeMaxDynamicSharedMemorySize, GSMEM);
    cudaFuncSetAttribute(attn_mma, cudaFuncAttributeMaxDynamicSharedMemorySize, ASMEM);

    split_x<<<4096, 256>>>(inputs_q);
    split_wt<<<dim3(32, 32, 4), dim3(32, 8)>>>(Wq, Wk, Wv, Wo);

    qkv_gemm<<<dim3(Fd / 128, (Bsz * Sq) / 128, 3), 256, GSMEM>>>(bq, bk, bv);

    attn_mma<<<dim3(Bsz, Hh * 16), 128, ASMEM>>>(R);

    out_gemm<<<dim3(Fd / 128, (Bsz * Sq) / 128), 256, GSMEM>>>(bo, out);
}

// round 16
// speedup vs baseline: 1.8256x; 1.0124x over previous
#include <cuda_runtime.h>
#include <cuda_bf16.h>
#include <math.h>
#include <stdint.h>

#define Bsz 4
#define Sq  1024
#define Fd  1024
#define Hh  16
#define Dd  64

// ---------------------------------------------------------------------------
// Scratch (device globals)
// ---------------------------------------------------------------------------
__device__ __nv_bfloat16 g_xhi[Bsz*Sq*Fd];
__device__ __nv_bfloat16 g_xlo[Bsz*Sq*Fd];
__device__ __nv_bfloat16 g_wthi[4*Fd*Fd];   // [N][K] x4 (Wq,Wk,Wv,Wo)
__device__ __nv_bfloat16 g_wtlo[4*Fd*Fd];
__device__ __nv_bfloat16 g_qh[Bsz*Hh*Sq*Dd];
__device__ __nv_bfloat16 g_ql[Bsz*Hh*Sq*Dd];
__device__ __nv_bfloat16 g_kh[Bsz*Hh*Sq*Dd];   // K single bf16 (softmax damps K error)
__device__ __nv_bfloat16 g_vh[Bsz*Hh*Sq*Dd];
__device__ __nv_bfloat16 g_vl[Bsz*Hh*Sq*Dd];
__device__ __nv_bfloat16 g_yhi[Bsz*Sq*Fd];
__device__ __nv_bfloat16 g_ylo[Bsz*Sq*Fd];

// ---------------------------------------------------------------------------
// PTX helpers (baseline PTX only)
// ---------------------------------------------------------------------------
__device__ __forceinline__ uint32_t smem_u32(const void* p) {
    uint32_t a;
    asm("{ .reg .u64 t; cvta.to.shared.u64 t, %1; cvt.u32.u64 %0, t; }"
        : "=r"(a) : "l"(p));
    return a;
}

// .cg: bypass L1 allocation (global data is smem-bound, never re-read via L1)
#define CPA(dst, src) do {                                                   \
    uint64_t _g = __cvta_generic_to_global((const void*)(src));              \
    asm volatile("cp.async.cg.shared.global [%0], [%1], 16;"                 \
                 :: "r"(dst), "l"(_g) : "memory");                           \
} while (0)
#define CPC() asm volatile("cp.async.commit_group;" ::: "memory")
#define CPW0() asm volatile("cp.async.wait_group 0;" ::: "memory")
#define CPW1() asm volatile("cp.async.wait_group 1;" ::: "memory")

__device__ __forceinline__ void ldsm4(uint32_t r[4], uint32_t addr) {
    asm volatile("ldmatrix.sync.aligned.m8n8.x4.shared.b16 {%0,%1,%2,%3}, [%4];"
        : "=r"(r[0]), "=r"(r[1]), "=r"(r[2]), "=r"(r[3]) : "r"(addr));
}
__device__ __forceinline__ void ldsm4t(uint32_t r[4], uint32_t addr) {
    asm volatile("ldmatrix.sync.aligned.m8n8.x4.trans.shared.b16 {%0,%1,%2,%3}, [%4];"
        : "=r"(r[0]), "=r"(r[1]), "=r"(r[2]), "=r"(r[3]) : "r"(addr));
}

__device__ __forceinline__ void mma16816(float* c, const uint32_t* a,
                                         uint32_t b0, uint32_t b1) {
    asm volatile("mma.sync.aligned.m16n8k16.row.col.f32.bf16.bf16.f32 "
        "{%0,%1,%2,%3}, {%4,%5,%6,%7}, {%8,%9}, {%0,%1,%2,%3};"
        : "+f"(c[0]), "+f"(c[1]), "+f"(c[2]), "+f"(c[3])
        : "r"(a[0]), "r"(a[1]), "r"(a[2]), "r"(a[3]), "r"(b0), "r"(b1));
}

// Truncation-based bf16 ops (cheap split: LOP3 + FADD + PRMT, no CVT)
__device__ __forceinline__ uint32_t packtrunc(float a, float b) {
    uint32_t r;
    asm("prmt.b32 %0, %1, %2, 0x7632;" : "=r"(r)
        : "r"(__float_as_uint(a)), "r"(__float_as_uint(b)));
    return r;
}
__device__ __forceinline__ float hitrunc(float x) {
    return __uint_as_float(__float_as_uint(x) & 0xffff0000u);
}

// ---------------------------------------------------------------------------
// Conversions
// ---------------------------------------------------------------------------
__global__ void split_x(const float* __restrict__ X) {
    int i = (blockIdx.x * blockDim.x + threadIdx.x) * 4;
    float4 v = *reinterpret_cast<const float4*>(&X[i]);
    float vv[4] = {v.x, v.y, v.z, v.w};
#pragma unroll
    for (int j = 0; j < 4; j++) {
        __nv_bfloat16 h = __float2bfloat16(vv[j]);
        g_xhi[i + j] = h;
        g_xlo[i + j] = __float2bfloat16(vv[j] - __bfloat162float(h));
    }
}

__global__ void split_wt(const float* __restrict__ Wq, const float* __restrict__ Wk,
                         const float* __restrict__ Wv, const float* __restrict__ Wo) {
    __shared__ float t[32][33];
    const int z = blockIdx.z;
    const float* __restrict__ W = (z == 0) ? Wq : (z == 1) ? Wk : (z == 2) ? Wv : Wo;
    __nv_bfloat16* hi = g_wthi + (size_t)z * Fd * Fd;
    __nv_bfloat16* lo = g_wtlo + (size_t)z * Fd * Fd;

    const int tx = threadIdx.x, ty = threadIdx.y;
    const int kbase = blockIdx.y * 32, nbase = blockIdx.x * 32;
#pragma unroll
    for (int i = 0; i < 4; i++) {
        int kr = ty * 4 + i;
        t[kr][tx] = W[(size_t)(kbase + kr) * Fd + nbase + tx];
    }
    __syncthreads();
#pragma unroll
    for (int i = 0; i < 4; i++) {
        int nr = ty * 4 + i;
        float v = t[tx][nr];
        __nv_bfloat16 h = __float2bfloat16(v);
        size_t o = (size_t)(nbase + nr) * Fd + kbase + tx;
        hi[o] = h;
        lo[o] = __float2bfloat16(v - __bfloat162float(h));
    }
}

// ---------------------------------------------------------------------------
// mma.sync GEMM: bf16 3-term hi/lo, 3-stage cp.async ring, XOR-swizzled smem.
// BM=128, BN=128, BK=32, 8 warps (2m x 4n), warp tile 64x32.
// MODE: 0 = fp32 C + bias. 1 = hi/lo bf16 [B,H,S,D]. 2 = hi-only bf16 [B,H,S,D].
// ---------------------------------------------------------------------------
#define GSTG  32768
#define GSMEM (3*GSTG)

template<int MODE>
__device__ __forceinline__ void gemm_mma(
    const __nv_bfloat16* __restrict__ Ahi, const __nv_bfloat16* __restrict__ Alo,
    const __nv_bfloat16* __restrict__ Bhi, const __nv_bfloat16* __restrict__ Blo,
    const float* __restrict__ bias, float scale,
    float* __restrict__ C, __nv_bfloat16* __restrict__ Chi,
    __nv_bfloat16* __restrict__ Clo,
    int m0, int n0)
{
    extern __shared__ __align__(128) char smem[];
    const uint32_t sb = smem_u32(smem);
    const int tid = threadIdx.x;
    const int lane = tid & 31, wid = tid >> 5;
    const int wm = (wid >> 2) * 64;
    const int wn = (wid & 3) * 32;

    float c[4][4][4];
#pragma unroll
    for (int i = 0; i < 4; i++)
#pragma unroll
        for (int j = 0; j < 4; j++)
#pragma unroll
            for (int r = 0; r < 4; r++) c[i][j][r] = 0.0f;

    const char* pAh = (const char*)Ahi;
    const char* pAl = (const char*)Alo;
    const char* pBh = (const char*)Bhi;
    const char* pBl = (const char*)Blo;

    auto load_stage = [&](int it) {
        const int k0 = it * 32;
        const uint32_t sbase = sb + (uint32_t)(it % 3) * GSTG;
#pragma unroll
        for (int t = 0; t < 2; t++) {
            int idx = tid + t * 256;
            int row = idx >> 2;
            int c16 = idx & 3;
            uint32_t sw = (uint32_t)(row * 64 + ((c16 ^ ((row >> 1) & 3)) * 16));
            size_t goA = ((size_t)(m0 + row) * Fd + k0) * 2 + c16 * 16;
            size_t goB = ((size_t)(n0 + row) * Fd + k0) * 2 + c16 * 16;
            CPA(sbase +     0 + sw, pAh + goA);
            CPA(sbase +  8192 + sw, pAl + goA);
            CPA(sbase + 16384 + sw, pBh + goB);
            CPA(sbase + 24576 + sw, pBl + goB);
        }
        CPC();
    };

    const int g = lane >> 3, r8 = lane & 7;

    auto compute = [&](uint32_t sbase) {
        const uint32_t abase = sbase;
        const uint32_t bbase = sbase + 16384;
#pragma unroll
        for (int ks = 0; ks < 2; ks++) {
            uint32_t ah[16], al[16];
            const int arow = (g & 1) * 8 + r8;
            const int ac16 = 2 * ks + (g >> 1);
#pragma unroll
            for (int mi = 0; mi < 4; mi++) {
                int r = wm + mi * 16 + arow;
                uint32_t sw = (uint32_t)(r * 64 + ((ac16 ^ ((r >> 1) & 3)) * 16));
                ldsm4(&ah[mi * 4], abase + sw);
                ldsm4(&al[mi * 4], abase + 8192 + sw);
            }
#pragma unroll
            for (int j2 = 0; j2 < 2; j2++) {
                uint32_t bh[4], bl[4];
                int br = wn + (2 * j2 + (g >> 1)) * 8 + r8;
                int bc16 = 2 * ks + (g & 1);
                uint32_t sw = (uint32_t)(br * 64 + ((bc16 ^ ((br >> 1) & 3)) * 16));
                ldsm4(bh, bbase + sw);
                ldsm4(bl, bbase + 8192 + sw);
#pragma unroll
                for (int mi = 0; mi < 4; mi++) {
                    mma16816(c[mi][2*j2],     &ah[mi * 4], bh[0], bh[1]);
                    mma16816(c[mi][2*j2 + 1], &ah[mi * 4], bh[2], bh[3]);
                }
#pragma unroll
                for (int mi = 0; mi < 4; mi++) {
                    mma16816(c[mi][2*j2],     &ah[mi * 4], bl[0], bl[1]);
                    mma16816(c[mi][2*j2 + 1], &ah[mi * 4], bl[2], bl[3]);
                }
#pragma unroll
                for (int mi = 0; mi < 4; mi++) {
                    mma16816(c[mi][2*j2],     &al[mi * 4], bh[0], bh[1]);
                    mma16816(c[mi][2*j2 + 1], &al[mi * 4], bh[2], bh[3]);
                }
            }
        }
    };

    load_stage(0);
    load_stage(1);
    for (int it = 0; it < Fd / 32; it++) {
        CPW1();
        __syncthreads();
        if (it + 2 < Fd / 32) load_stage(it + 2);
        compute(sb + (uint32_t)(it % 3) * GSTG);
    }

    const int crow = lane >> 2;
    const int ccol = (lane & 3) * 2;
#pragma unroll
    for (int mi = 0; mi < 4; mi++) {
#pragma unroll
        for (int nj = 0; nj < 4; nj++) {
            const int m = m0 + wm + mi * 16 + crow;
            const int n = n0 + wn + nj * 8 + ccol;
            const float b0 = __ldg(&bias[n]);
            const float b1 = __ldg(&bias[n + 1]);
            float v00 = (c[mi][nj][0] + b0) * scale;
            float v01 = (c[mi][nj][1] + b1) * scale;
            float v10 = (c[mi][nj][2] + b0) * scale;
            float v11 = (c[mi][nj][3] + b1) * scale;
            if (MODE == 0) {
                float2 o0 = {v00, v01}, o1 = {v10, v11};
                *reinterpret_cast<float2*>(&C[(size_t)m * Fd + n]) = o0;
                *reinterpret_cast<float2*>(&C[(size_t)(m + 8) * Fd + n]) = o1;
            } else {
                const int bb = m >> 10, ss = m & 1023;
                const int hh = n >> 6, dd = n & 63;
                size_t off0 = (((size_t)(bb * Hh + hh)) * Sq + ss) * Dd + dd;
                size_t off1 = off0 + 8 * Dd;
                __nv_bfloat16 h00 = __float2bfloat16(v00);
                __nv_bfloat16 h01 = __float2bfloat16(v01);
                __nv_bfloat16 h10 = __float2bfloat16(v10);
                __nv_bfloat16 h11 = __float2bfloat16(v11);
                __nv_bfloat162 hp0 = __nv_bfloat162(h00, h01);
                __nv_bfloat162 hp1 = __nv_bfloat162(h10, h11);
                *reinterpret_cast<uint32_t*>(&Chi[off0]) = *reinterpret_cast<uint32_t*>(&hp0);
                *reinterpret_cast<uint32_t*>(&Chi[off1]) = *reinterpret_cast<uint32_t*>(&hp1);
                if (MODE == 1) {
                    __nv_bfloat162 lp0 = __nv_bfloat162(
                        __float2bfloat16(v00 - __bfloat162float(h00)),
                        __float2bfloat16(v01 - __bfloat162float(h01)));
                    __nv_bfloat162 lp1 = __nv_bfloat162(
                        __float2bfloat16(v10 - __bfloat162float(h10)),
                        __float2bfloat16(v11 - __bfloat162float(h11)));
                    *reinterpret_cast<uint32_t*>(&Clo[off0]) = *reinterpret_cast<uint32_t*>(&lp0);
                    *reinterpret_cast<uint32_t*>(&Clo[off1]) = *reinterpret_cast<uint32_t*>(&lp1);
                }
            }
        }
    }
}

__global__ __launch_bounds__(256, 2) void qkv_gemm(
    const float* __restrict__ bq, const float* __restrict__ bk,
    const float* __restrict__ bv)
{
    const int z = blockIdx.z;
    const int m0 = blockIdx.y * 128, n0 = blockIdx.x * 128;
    if (z == 0) {
        gemm_mma<1>(g_xhi, g_xlo, g_wthi, g_wtlo, bq, 0.125f,
                    nullptr, g_qh, g_ql, m0, n0);
    } else if (z == 1) {
        gemm_mma<2>(g_xhi, g_xlo, g_wthi + (size_t)Fd * Fd, g_wtlo + (size_t)Fd * Fd,
                    bk, 1.0f, nullptr, g_kh, nullptr, m0, n0);
    } else {
        gemm_mma<1>(g_xhi, g_xlo, g_wthi + (size_t)2 * Fd * Fd, g_wtlo + (size_t)2 * Fd * Fd,
                    bv, 1.0f, nullptr, g_vh, g_vl, m0, n0);
    }
}

__global__ __launch_bounds__(256, 2) void out_gemm(
    const float* __restrict__ bo, float* __restrict__ out)
{
    gemm_mma<0>(g_yhi, g_ylo,
                g_wthi + (size_t)3 * Fd * Fd, g_wtlo + (size_t)3 * Fd * Fd,
                bo, 1.0f, out, nullptr, nullptr,
                blockIdx.y * 128, blockIdx.x * 128);
}

// ---------------------------------------------------------------------------
// Flash attention: no-max softmax, R via __ldg, K single bf16 (2-term QK),
// V hi/lo (3-term PV). Truncation-based P split (LOP3/FADD/PRMT, no CVT).
// 64 q-rows/CTA, 32-key tiles, 2-stage ring, wait-after-compute. 4 CTAs/SM.
// ---------------------------------------------------------------------------
#define AKH 0
#define AVH 4608
#define AVL 9216
#define ASTG 13824
#define AQH  (2*ASTG)
#define AQL  (AQH + 9216)
#define ASMEM (AQL + 9216)
#define KVPITCH 144
#define NKT 32

__global__ __launch_bounds__(128, 4) void attn_mma(const float* __restrict__ R)
{
    extern __shared__ __align__(128) char smem[];
    const uint32_t sb = smem_u32(smem);
    const int tid = threadIdx.x;
    const int lane = tid & 31, w = tid >> 5;
    const int bb = blockIdx.x;
    const int hh = blockIdx.y >> 4;
    const int qt = blockIdx.y & 15;
    const int bh = bb * Hh + hh;

    const int lr = lane & 7;
    const int sel8  = (lane & 8) ? 8 : 0;
    const int sel16 = (lane & 16) ? 8 : 0;
    const int crow = lane >> 2;
    const int ct = (lane & 3) * 2;

    const __nv_bfloat16* Kh = g_kh + (size_t)bh * Sq * Dd;
    const __nv_bfloat16* Vh = g_vh + (size_t)bh * Sq * Dd;
    const __nv_bfloat16* Vl = g_vl + (size_t)bh * Sq * Dd;
    const int rrow0 = w * 16 + crow;
    const float* Rrow0 = R + (size_t)hh * Sq * Sq + (size_t)(qt * 64 + rrow0) * Sq;
    const float* Rrow1 = Rrow0 + 8 * (size_t)Sq;

    auto load_stage = [&](int stg, int kt) {
        const int k0 = kt * 32;
        const uint32_t sbase = sb + stg * ASTG;
#pragma unroll
        for (int i = 0; i < 2; i++) {
            int idx = tid + i * 128;
            int row = idx >> 3;
            int seg = (idx & 7) * 16;
            uint32_t so = sbase + row * KVPITCH + seg;
            size_t go = ((size_t)(k0 + row)) * Dd + (seg >> 1);
            CPA(so + AKH, Kh + go);
            CPA(so + AVH, Vh + go);
            CPA(so + AVL, Vl + go);
        }
        CPC();
    };

    // ---- stage-0 prefetch + Q staging into dedicated region ----
    load_stage(0, 0);
    {
        const __nv_bfloat16* Qh = g_qh + ((size_t)bh * Sq + qt * 64) * Dd;
        const __nv_bfloat16* Ql = g_ql + ((size_t)bh * Sq + qt * 64) * Dd;
#pragma unroll
        for (int i = 0; i < 4; i++) {
            int idx = tid + i * 128;
            int row = idx >> 3;
            int seg = (idx & 7) * 16;
            uint32_t so = sb + AQH + row * KVPITCH + seg;
            size_t go = (size_t)row * Dd + (seg >> 1);
            CPA(so, Qh + go);
            CPA(so + 9216, Ql + go);
        }
        CPC();
    }
    CPW0();
    __syncthreads();

    uint32_t qfh[4][4], qfl[4][4];
    {
        const int arow = w * 16 + lr + sel8;
#pragma unroll
        for (int cc = 0; cc < 4; cc++) {
            const int acol = cc * 16 + sel16;
            uint32_t ad = sb + AQH + (uint32_t)(arow * KVPITCH + acol * 2);
            ldsm4(qfh[cc], ad);
            ldsm4(qfl[cc], ad + 9216);
        }
    }

    float o[8][4];
#pragma unroll
    for (int j = 0; j < 8; j++)
#pragma unroll
        for (int r = 0; r < 4; r++) o[j][r] = 0.0f;
    float lval0 = 0.0f, lval1 = 0.0f;

    for (int kt = 0; kt < NKT; kt++) {
        if (kt + 1 < NKT) load_stage((kt + 1) & 1, kt + 1);
        const uint32_t stg = sb + (kt & 1) * ASTG;
        const int k0 = kt * 32;

        // ---- prefetch R via LDG (hidden under QK MMAs) ----
        float2 rv0[4], rv1[4];
#pragma unroll
        for (int j = 0; j < 4; j++) {
            const int cj = k0 + j * 8 + ct;
            rv0[j] = __ldg(reinterpret_cast<const float2*>(Rrow0 + cj));
            rv1[j] = __ldg(reinterpret_cast<const float2*>(Rrow1 + cj));
        }

        // ---- QK^T (2 terms: qh*k + ql*k; K single bf16) ----
        float c[4][4];
#pragma unroll
        for (int j = 0; j < 4; j++)
#pragma unroll
            for (int r = 0; r < 4; r++) c[j][r] = 0.0f;

#pragma unroll
        for (int cc = 0; cc < 4; cc++) {
            const int bcol = cc * 16 + sel8;
            uint32_t kh0[4], kh1[4];
            {
                uint32_t kd0 = stg + (uint32_t)((lr + sel16) * KVPITCH + bcol * 2);
                uint32_t kd1 = stg + (uint32_t)((16 + lr + sel16) * KVPITCH + bcol * 2);
                ldsm4(kh0, kd0 + AKH);
                ldsm4(kh1, kd1 + AKH);
            }
            mma16816(c[0], qfh[cc], kh0[0], kh0[1]);
            mma16816(c[1], qfh[cc], kh0[2], kh0[3]);
            mma16816(c[2], qfh[cc], kh1[0], kh1[1]);
            mma16816(c[3], qfh[cc], kh1[2], kh1[3]);
            mma16816(c[0], qfl[cc], kh0[0], kh0[1]);
            mma16816(c[1], qfl[cc], kh0[2], kh0[3]);
            mma16816(c[2], qfl[cc], kh1[0], kh1[1]);
            mma16816(c[3], qfl[cc], kh1[2], kh1[3]);
        }

        // ---- add R, exp, truncation-split P (no CVT chain) ----
        uint32_t pah[2][4], pal[2][4];
#pragma unroll
        for (int j = 0; j < 4; j++) {
            float p00 = __expf(c[j][0] + rv0[j].x);
            float p01 = __expf(c[j][1] + rv0[j].y);
            float p10 = __expf(c[j][2] + rv1[j].x);
            float p11 = __expf(c[j][3] + rv1[j].y);
            lval0 += p00 + p01;
            lval1 += p10 + p11;
            const int kc = j >> 1, sl = (j & 1) * 2;
            pah[kc][sl]   = packtrunc(p00, p01);
            pah[kc][sl+1] = packtrunc(p10, p11);
            pal[kc][sl]   = packtrunc(p00 - hitrunc(p00), p01 - hitrunc(p01));
            pal[kc][sl+1] = packtrunc(p10 - hitrunc(p10), p11 - hitrunc(p11));
        }

        // ---- P @ V (3 terms: ph*vh + ph*vl + pl*vh) ----
#pragma unroll
        for (int kc = 0; kc < 2; kc++) {
            const int vrow = kc * 16 + lr + sel8;
#pragma unroll
            for (int npp = 0; npp < 4; npp += 2) {
                uint32_t vhA[4], vlA[4], vhB[4], vlB[4];
                uint32_t vdA = stg + (uint32_t)(vrow * KVPITCH + (npp * 16 + sel16) * 2);
                uint32_t vdB = stg + (uint32_t)(vrow * KVPITCH + ((npp + 1) * 16 + sel16) * 2);
                ldsm4t(vhA, vdA + AVH);
                ldsm4t(vlA, vdA + AVL);
                ldsm4t(vhB, vdB + AVH);
                ldsm4t(vlB, vdB + AVL);
                mma16816(o[2*npp],     pah[kc], vhA[0], vhA[1]);
                mma16816(o[2*npp + 1], pah[kc], vhA[2], vhA[3]);
                mma16816(o[2*npp + 2], pah[kc], vhB[0], vhB[1]);
                mma16816(o[2*npp + 3], pah[kc], vhB[2], vhB[3]);
                mma16816(o[2*npp],     pah[kc], vlA[0], vlA[1]);
                mma16816(o[2*npp + 1], pah[kc], vlA[2], vlA[3]);
                mma16816(o[2*npp + 2], pah[kc], vlB[0], vlB[1]);
                mma16816(o[2*npp + 3], pah[kc], vlB[2], vlB[3]);
                mma16816(o[2*npp],     pal[kc], vhA[0], vhA[1]);
                mma16816(o[2*npp + 1], pal[kc], vhA[2], vhA[3]);
                mma16816(o[2*npp + 2], pal[kc], vhB[0], vhB[1]);
                mma16816(o[2*npp + 3], pal[kc], vhB[2], vhB[3]);
            }
        }

        CPW0();
        __syncthreads();
    }

    // ---- single cross-lane reduction of l, normalize, write ----
    lval0 += __shfl_xor_sync(0xffffffffu, lval0, 1);
    lval0 += __shfl_xor_sync(0xffffffffu, lval0, 2);
    lval1 += __shfl_xor_sync(0xffffffffu, lval1, 1);
    lval1 += __shfl_xor_sync(0xffffffffu, lval1, 2);
    const float inv0 = 1.0f / lval0;
    const float inv1 = 1.0f / lval1;
    const int row0 = bb * Sq + qt * 64 + w * 16 + crow;
#pragma unroll
    for (int j = 0; j < 8; j++) {
        const int col = hh * Dd + j * 8 + ct;
        float v00 = o[j][0] * inv0, v01 = o[j][1] * inv0;
        float v10 = o[j][2] * inv1, v11 = o[j][3] * inv1;
        __nv_bfloat16 h00 = __float2bfloat16(v00);
        __nv_bfloat16 h01 = __float2bfloat16(v01);
        __nv_bfloat16 h10 = __float2bfloat16(v10);
        __nv_bfloat16 h11 = __float2bfloat16(v11);
        __nv_bfloat162 hp0 = __nv_bfloat162(h00, h01);
        __nv_bfloat162 hp1 = __nv_bfloat162(h10, h11);
        __nv_bfloat162 lp0 = __nv_bfloat162(
            __float2bfloat16(v00 - __bfloat162float(h00)),
            __float2bfloat16(v01 - __bfloat162float(h01)));
        __nv_bfloat162 lp1 = __nv_bfloat162(
            __float2bfloat16(v10 - __bfloat162float(h10)),
            __float2bfloat16(v11 - __bfloat162float(h11)));
        size_t off0 = (size_t)row0 * Fd + col;
        size_t off1 = off0 + 8 * (size_t)Fd;
        *reinterpret_cast<uint32_t*>(&g_yhi[off0]) = *reinterpret_cast<uint32_t*>(&hp0);
        *reinterpret_cast<uint32_t*>(&g_yhi[off1]) = *reinterpret_cast<uint32_t*>(&hp1);
        *reinterpret_cast<uint32_t*>(&g_ylo[off0]) = *reinterpret_cast<uint32_t*>(&lp0);
        *reinterpret_cast<uint32_t*>(&g_ylo[off1]) = *reinterpret_cast<uint32_t*>(&lp1);
    }
}

// ---------------------------------------------------------------------------
extern "C" void kernel_launch(void* const* d_in, const int* in_sizes, int n_in,
                              void* d_out, int out_size)
{
    const float* inputs_q = (const float*)d_in[0];
    const float* Wq = (const float*)d_in[1];
    const float* bq = (const float*)d_in[2];
    const float* Wk = (const float*)d_in[3];
    const float* bk = (const float*)d_in[4];
    const float* Wv = (const float*)d_in[5];
    const float* bv = (const float*)d_in[6];
    const float* R  = (const float*)d_in[7];
    const float* Wo = (const float*)d_in[8];
    const float* bo = (const float*)d_in[9];
    float* out = (float*)d_out;

    cudaFuncSetAttribute(qkv_gemm, cudaFuncAttributeMaxDynamicSharedMemorySize, GSMEM);
    cudaFuncSetAttribute(out_gemm, cudaFuncAttributeMaxDynamicSharedMemorySize, GSMEM);
    cudaFuncSetAttribute(attn_mma, cudaFuncAttributeMaxDynamicSharedMemorySize, ASMEM);

    split_x<<<4096, 256>>>(inputs_q);
    split_wt<<<dim3(32, 32, 4), dim3(32, 8)>>>(Wq, Wk, Wv, Wo);

    qkv_gemm<<<dim3(Fd / 128, (Bsz * Sq) / 128, 3), 256, GSMEM>>>(bq, bk, bv);

    attn_mma<<<dim3(Bsz, Hh * 16), 128, ASMEM>>>(R);

    out_gemm<<<dim3(Fd / 128, (Bsz * Sq) / 128), 256, GSMEM>>>(bo, out);
}